// round 9
// baseline (speedup 1.0000x reference)
#include <cuda_runtime.h>
#include <cuda_bf16.h>
#include <cstdint>
#include <math.h>

// Problem constants
#define B_  1
#define S_  2048
#define H_  2048
#define NH_ 8
#define DH_ 256
#define SCALE_ 0.0625f   // 256^-0.5
#define NEG_  -1000000000.0f

typedef __nv_bfloat16 bf16;

// ================= helpers =====================================================
__device__ __forceinline__ uint32_t smem_to_u32(const void* smem_ptr) {
    uint32_t addr;
    asm("{ .reg .u64 tmp; cvta.to.shared.u64 tmp, %1; cvt.u32.u64 %0, tmp; }"
        : "=r"(addr) : "l"(smem_ptr));
    return addr;
}

__device__ __forceinline__ void cp_async16(uint32_t dst, const void* src) {
    asm volatile("cp.async.cg.shared.global [%0], [%1], 16;\n"
                 :: "r"(dst), "l"(src) : "memory");
}

__device__ __forceinline__ void ldsm_x4(uint32_t r[4], uint32_t addr) {
    asm volatile("ldmatrix.sync.aligned.m8n8.x4.shared.b16 {%0,%1,%2,%3}, [%4];"
                 : "=r"(r[0]), "=r"(r[1]), "=r"(r[2]), "=r"(r[3]) : "r"(addr));
}

__device__ __forceinline__ void mma_bf16(float acc[4], const uint32_t a[4], const uint32_t b[2]) {
    asm volatile(
        "mma.sync.aligned.m16n8k16.row.col.f32.bf16.bf16.f32 "
        "{%0,%1,%2,%3}, {%4,%5,%6,%7}, {%8,%9}, {%0,%1,%2,%3};"
        : "+f"(acc[0]), "+f"(acc[1]), "+f"(acc[2]), "+f"(acc[3])
        : "r"(a[0]), "r"(a[1]), "r"(a[2]), "r"(a[3]), "r"(b[0]), "r"(b[1]));
}

__device__ __forceinline__ uint32_t pack_hi2(float v0, float v1) {
    bf16 h0 = __float2bfloat16(v0);
    bf16 h1 = __float2bfloat16(v1);
    return (uint32_t)__bfloat16_as_ushort(h0) | ((uint32_t)__bfloat16_as_ushort(h1) << 16);
}
__device__ __forceinline__ uint32_t pack_lo2(float v0, float v1) {
    bf16 h0 = __float2bfloat16(v0);
    bf16 h1 = __float2bfloat16(v1);
    bf16 l0 = __float2bfloat16(v0 - __bfloat162float(h0));
    bf16 l1 = __float2bfloat16(v1 - __bfloat162float(h1));
    return (uint32_t)__bfloat16_as_ushort(l0) | ((uint32_t)__bfloat16_as_ushort(l1) << 16);
}
__device__ __forceinline__ uint2 pack_hi4(float a, float b, float c, float d) {
    return make_uint2(pack_hi2(a, b), pack_hi2(c, d));
}
__device__ __forceinline__ uint2 pack_lo4(float a, float b, float c, float d) {
    return make_uint2(pack_lo2(a, b), pack_lo2(c, d));
}

// ================= scratch (device globals; no allocation) ====================
__device__ __align__(128) float g_Q  [S_ * H_];
__device__ __align__(128) float g_K  [S_ * DH_];
__device__ __align__(128) float g_V  [S_ * DH_];

__device__ __align__(128) bf16 g_xhi [S_ * H_];
__device__ __align__(128) bf16 g_xlo [S_ * H_];
__device__ __align__(128) bf16 g_wqThi[H_ * H_];
__device__ __align__(128) bf16 g_wqTlo[H_ * H_];
__device__ __align__(128) bf16 g_wkThi[DH_ * H_];
__device__ __align__(128) bf16 g_wkTlo[DH_ * H_];
__device__ __align__(128) bf16 g_wvThi[DH_ * H_];
__device__ __align__(128) bf16 g_wvTlo[DH_ * H_];
__device__ __align__(128) bf16 g_woThi[H_ * H_];
__device__ __align__(128) bf16 g_woTlo[H_ * H_];
__device__ __align__(128) bf16 g_qhi [S_ * H_];
__device__ __align__(128) bf16 g_qlo [S_ * H_];
__device__ __align__(128) bf16 g_khi [S_ * DH_];
__device__ __align__(128) bf16 g_klo [S_ * DH_];
__device__ __align__(128) bf16 g_vthi[DH_ * S_];
__device__ __align__(128) bf16 g_vtlo[DH_ * S_];
__device__ __align__(128) bf16 g_phi [(long long)NH_ * S_ * S_];
__device__ __align__(128) bf16 g_plo [(long long)NH_ * S_ * S_];
__device__ __align__(128) bf16 g_chi [S_ * H_];
__device__ __align__(128) bf16 g_clo [S_ * H_];

// ================= split-bf16 mma.sync GEMM, 4-stage pipeline =================
// C = (Ahi+Alo) @ (Bhi+Blo)^T via 3 HMMA passes, fp32 accum.
// K-chunk 16, 4 smem stages, ONE __syncthreads per stage, cp.async 3-ahead.
template<int NT8>
__global__ __launch_bounds__(256, 2)
void mma_gemm(const bf16* __restrict__ Ahi, const bf16* __restrict__ Alo,
              const bf16* __restrict__ Bhi, const bf16* __restrict__ Blo,
              float* __restrict__ C,
              bf16* __restrict__ Chi, bf16* __restrict__ Clo,
              int K, int lda, int ldb, int ldc,
              long long aStride, long long bStride, long long cStride,
              int mode)
{
    constexpr int TN     = NT8 * 32;
    constexpr int ROW    = 24;                 // bf16 per smem row (48B, conflict-free)
    constexpr int A_TILE = 128 * ROW;          // elems
    constexpr int B_TILE = TN * ROW;
    constexpr int STAGE  = 2 * A_TILE + 2 * B_TILE;

    const int rowBase = blockIdx.y * 128;
    const int colBase = blockIdx.x * TN;

    if ((mode & 1) && colBase > rowBase + 127) return;

    int Keff = K;
    if (mode & 2) Keff = min(K, rowBase + 128);

    extern __shared__ bf16 smem[];
    const uint32_t sbase = smem_to_u32(smem);

    const int tid  = threadIdx.x;
    const int wid  = tid >> 5;
    const int lane = tid & 31;
    const int wm   = wid & 1;
    const int wn   = wid >> 1;

    Ahi += (long long)blockIdx.z * aStride;
    Alo += (long long)blockIdx.z * aStride;
    Bhi += (long long)blockIdx.z * bStride;
    Blo += (long long)blockIdx.z * bStride;

    float acc[4][NT8][4] = {};

    const int nStages = Keff >> 4;             // K-chunk = 16

    // loader: A 128 rows x 2 chunks of 16B -> 1 cp per operand per thread
    const int lrow = tid >> 1;
    const int lch  = tid & 1;

    auto issue = [&](int s) {
        const uint32_t sb = sbase + (uint32_t)(s & 3) * STAGE * 2;
        const int kt = s << 4;
        {
            const long long g = (long long)(rowBase + lrow) * lda + kt + lch * 8;
            const uint32_t d = sb + (uint32_t)(lrow * ROW + lch * 8) * 2;
            cp_async16(d,              Ahi + g);
            cp_async16(d + A_TILE * 2, Alo + g);
        }
        if (TN == 128 || tid < 128) {
            const long long g = (long long)(colBase + lrow) * ldb + kt + lch * 8;
            const uint32_t d = sb + (uint32_t)(2 * A_TILE + lrow * ROW + lch * 8) * 2;
            cp_async16(d,              Bhi + g);
            cp_async16(d + B_TILE * 2, Blo + g);
        }
        asm volatile("cp.async.commit_group;\n" ::: "memory");
    };

    issue(0);
    if (1 < nStages) issue(1);
    if (2 < nStages) issue(2);

    for (int s = 0; s < nStages; s++) {
        const int remain = nStages - 1 - s;     // groups issued after s
        if (remain >= 2)      asm volatile("cp.async.wait_group 2;\n" ::: "memory");
        else if (remain == 1) asm volatile("cp.async.wait_group 1;\n" ::: "memory");
        else                  asm volatile("cp.async.wait_group 0;\n" ::: "memory");
        __syncthreads();

        const uint32_t sb = sbase + (uint32_t)(s & 3) * STAGE * 2;
        const uint32_t sA = sb;
        const uint32_t sB = sb + 2 * A_TILE * 2;

        // ---- B fragments: ldmatrix.x4 covers 2 nt tiles x 2 k-halves ----
        uint32_t bh[NT8][2], bl[NT8][2];
        {
            const int brow4 = wn * (NT8 * 8) + ((lane >> 4) << 3) + (lane & 7);
            const int bcol4 = (((lane >> 3) & 1) << 3);
            #pragma unroll
            for (int ntp = 0; ntp < NT8 / 2; ntp++) {
                const uint32_t addr =
                    sB + (uint32_t)((brow4 + ntp * 16) * ROW + bcol4) * 2;
                uint32_t rh[4], rl[4];
                ldsm_x4(rh, addr);
                ldsm_x4(rl, addr + B_TILE * 2);
                bh[2 * ntp][0] = rh[0]; bh[2 * ntp][1] = rh[1];
                bh[2 * ntp + 1][0] = rh[2]; bh[2 * ntp + 1][1] = rh[3];
                bl[2 * ntp][0] = rl[0]; bl[2 * ntp][1] = rl[1];
                bl[2 * ntp + 1][0] = rl[2]; bl[2 * ntp + 1][1] = rl[3];
            }
        }
        // ---- per-mt A fragments + MMA ----
        const int arow = wm * 64 + (lane & 15);
        const int acol = ((lane >> 4) << 3);
        #pragma unroll
        for (int mt = 0; mt < 4; mt++) {
            uint32_t ah[4], al[4];
            const uint32_t addr = sA + (uint32_t)((arow + mt * 16) * ROW + acol) * 2;
            ldsm_x4(ah, addr);
            ldsm_x4(al, addr + A_TILE * 2);
            #pragma unroll
            for (int nt = 0; nt < NT8; nt++) {
                mma_bf16(acc[mt][nt], ah, bh[nt]);
                mma_bf16(acc[mt][nt], ah, bl[nt]);
                mma_bf16(acc[mt][nt], al, bh[nt]);
            }
        }

        if (s + 3 < nStages) issue(s + 3);
    }

    const int erow0 = rowBase + wm * 64 + (lane >> 2);
    const int ecol0 = colBase + wn * (NT8 * 8) + (lane & 3) * 2;
    #pragma unroll
    for (int mt = 0; mt < 4; mt++) {
        #pragma unroll
        for (int nt = 0; nt < NT8; nt++) {
            const int r = erow0 + mt * 16;
            const int c = ecol0 + nt * 8;
            if (C) {
                float* Cb = C + (long long)blockIdx.z * cStride;
                *(float2*)&Cb[(long long)r * ldc + c] =
                    make_float2(acc[mt][nt][0], acc[mt][nt][1]);
                *(float2*)&Cb[(long long)(r + 8) * ldc + c] =
                    make_float2(acc[mt][nt][2], acc[mt][nt][3]);
            }
            if (Chi) {
                bf16* Hb = Chi + (long long)blockIdx.z * cStride;
                bf16* Lb = Clo + (long long)blockIdx.z * cStride;
                *(uint32_t*)&Hb[(long long)r * ldc + c] = pack_hi2(acc[mt][nt][0], acc[mt][nt][1]);
                *(uint32_t*)&Lb[(long long)r * ldc + c] = pack_lo2(acc[mt][nt][0], acc[mt][nt][1]);
                *(uint32_t*)&Hb[(long long)(r + 8) * ldc + c] = pack_hi2(acc[mt][nt][2], acc[mt][nt][3]);
                *(uint32_t*)&Lb[(long long)(r + 8) * ldc + c] = pack_lo2(acc[mt][nt][2], acc[mt][nt][3]);
            }
        }
    }
}

// ================= fp32 -> bf16 hi/lo split (float4 vectorized) ===============
__global__ void split_kernel(const float4* __restrict__ in,
                             uint2* __restrict__ hi, uint2* __restrict__ lo,
                             long long n4)
{
    long long i = (long long)blockIdx.x * blockDim.x + threadIdx.x;
    if (i >= n4) return;
    float4 v = in[i];
    hi[i] = pack_hi4(v.x, v.y, v.z, v.w);
    lo[i] = pack_lo4(v.x, v.y, v.z, v.w);
}

// transpose + split: in[R][C] fp32 -> hiT/loT [C][R] bf16 (vectorized)
__global__ void tsplit_kernel(const float* __restrict__ in,
                              bf16* __restrict__ hiT, bf16* __restrict__ loT,
                              int R, int C)
{
    __shared__ float tile[32][36];
    const int c0 = blockIdx.x * 32;
    const int r0 = blockIdx.y * 32;
    const int tx = threadIdx.x;
    const int ty = threadIdx.y;

    {
        float4 v = *(const float4*)&in[(long long)(r0 + tx) * C + c0 + ty * 4];
        *(float4*)&tile[tx][ty * 4] = v;
    }
    __syncthreads();
    {
        float a = tile[ty * 4 + 0][tx];
        float b = tile[ty * 4 + 1][tx];
        float c = tile[ty * 4 + 2][tx];
        float d = tile[ty * 4 + 3][tx];
        const long long o = (long long)(c0 + tx) * R + r0 + ty * 4;
        *(uint2*)&hiT[o] = pack_hi4(a, b, c, d);
        *(uint2*)&loT[o] = pack_lo4(a, b, c, d);
    }
}

// ================= RoPE (vectorized: 4 pairs per thread) ======================
__global__ void rope_split_kernel(const float* __restrict__ src,
                                  bf16* __restrict__ hi, bf16* __restrict__ lo,
                                  const int* __restrict__ pos,
                                  int nHeads, int rowStride)
{
    long long idx = (long long)blockIdx.x * blockDim.x + threadIdx.x;
    const long long total = (long long)S_ * nHeads * 32;
    if (idx >= total) return;
    const int d4 = (int)(idx & 31) * 4;
    const int h  = (int)((idx >> 5) % nHeads);
    const int s  = (int)(idx / (32LL * nHeads));

    const float p = (float)pos[s];
    const long long base = (long long)s * rowStride + h * DH_;

    float4 a = *(const float4*)&src[base + d4];
    float4 b = *(const float4*)&src[base + d4 + 128];

    float ra[4], rb[4];
    const float av[4] = {a.x, a.y, a.z, a.w};
    const float bv[4] = {b.x, b.y, b.z, b.w};
    #pragma unroll
    for (int k = 0; k < 4; k++) {
        const int d = d4 + k;
        float inv = exp2f(-((float)(2 * d) / (float)DH_) * log2f(10000.0f));
        float ang = p * inv;
        float sn, cs;
        sincosf(ang, &sn, &cs);
        ra[k] = av[k] * cs - bv[k] * sn;
        rb[k] = bv[k] * cs + av[k] * sn;
    }

    *(uint2*)&hi[base + d4]       = pack_hi4(ra[0], ra[1], ra[2], ra[3]);
    *(uint2*)&lo[base + d4]       = pack_lo4(ra[0], ra[1], ra[2], ra[3]);
    *(uint2*)&hi[base + d4 + 128] = pack_hi4(rb[0], rb[1], rb[2], rb[3]);
    *(uint2*)&lo[base + d4 + 128] = pack_lo4(rb[0], rb[1], rb[2], rb[3]);
}

// ================= causal scale + softmax (prefix-only reads) ==================
__global__ void softmax_kernel(float* __restrict__ attn,
                               bf16* __restrict__ phi, bf16* __restrict__ plo)
{
    const int i = blockIdx.x;
    const int h = blockIdx.y;
    const long long rowOff = ((long long)h * S_ + i) * S_;
    float* row = attn + rowOff;
    const int t = threadIdx.x;
    const int lane = t & 31, warp = t >> 5;

    const int kLimit = ((i >> 7) + 1) << 7;

    float vals[8];
    float mx = -INFINITY;
    #pragma unroll
    for (int j = 0; j < 2; j++) {
        const int col4 = 4 * t + j * 1024;
        if (col4 <= i) {
            float4 v = *(const float4*)&row[col4];
            const float vv[4] = {v.x, v.y, v.z, v.w};
            #pragma unroll
            for (int k = 0; k < 4; k++) {
                const int col = col4 + k;
                float u = (col <= i) ? fmaf(vv[k], SCALE_, 0.0f) : NEG_;
                vals[j * 4 + k] = u;
                mx = fmaxf(mx, u);
            }
        } else {
            #pragma unroll
            for (int k = 0; k < 4; k++) vals[j * 4 + k] = NEG_;
        }
    }

    __shared__ float red[8];
    #pragma unroll
    for (int o = 16; o > 0; o >>= 1)
        mx = fmaxf(mx, __shfl_xor_sync(0xffffffffu, mx, o));
    if (lane == 0) red[warp] = mx;
    __syncthreads();
    {
        float m = red[lane & 7];
        #pragma unroll
        for (int o = 4; o > 0; o >>= 1)
            m = fmaxf(m, __shfl_xor_sync(0xffffffffu, m, o));
        mx = m;
    }

    float sum = 0.0f;
    #pragma unroll
    for (int j = 0; j < 8; j++) {
        vals[j] = __expf(vals[j] - mx);
        sum += vals[j];
    }
    #pragma unroll
    for (int o = 16; o > 0; o >>= 1)
        sum += __shfl_xor_sync(0xffffffffu, sum, o);
    __syncthreads();
    if (lane == 0) red[warp] = sum;
    __syncthreads();
    {
        float m = red[lane & 7];
        #pragma unroll
        for (int o = 4; o > 0; o >>= 1)
            m += __shfl_xor_sync(0xffffffffu, m, o);
        sum = m;
    }

    const float inv = 1.0f / sum;
    #pragma unroll
    for (int j = 0; j < 2; j++) {
        const int col4 = 4 * t + j * 1024;
        float p0 = vals[j * 4 + 0] * inv;
        float p1 = vals[j * 4 + 1] * inv;
        float p2 = vals[j * 4 + 2] * inv;
        float p3 = vals[j * 4 + 3] * inv;
        *(float4*)&row[col4] = make_float4(p0, p1, p2, p3);
        if (col4 < kLimit) {
            *(uint2*)&phi[rowOff + col4] = pack_hi4(p0, p1, p2, p3);
            *(uint2*)&plo[rowOff + col4] = pack_lo4(p0, p1, p2, p3);
        }
    }
}

// ================= launch ======================================================
static void* sym_addr(const void* sym)
{
    void* p = nullptr;
    cudaGetSymbolAddress(&p, sym);
    return p;
}

extern "C" void kernel_launch(void* const* d_in, const int* in_sizes, int n_in,
                              void* d_out, int out_size)
{
    const float* x    = (const float*)d_in[0];
    const int*   pos  = (const int*)  d_in[1];
    const float* wq   = (const float*)d_in[3];
    const float* wk   = (const float*)d_in[4];
    const float* wv   = (const float*)d_in[5];
    const float* wo   = (const float*)d_in[6];

    float* out  = (float*)d_out;
    float* attn = out + (long long)B_ * S_ * H_;

    float* Qf = (float*)sym_addr(g_Q);
    float* Kf = (float*)sym_addr(g_K);
    float* Vf = (float*)sym_addr(g_V);

    bf16* xhi   = (bf16*)sym_addr(g_xhi);
    bf16* xlo   = (bf16*)sym_addr(g_xlo);
    bf16* wqThi = (bf16*)sym_addr(g_wqThi);
    bf16* wqTlo = (bf16*)sym_addr(g_wqTlo);
    bf16* wkThi = (bf16*)sym_addr(g_wkThi);
    bf16* wkTlo = (bf16*)sym_addr(g_wkTlo);
    bf16* wvThi = (bf16*)sym_addr(g_wvThi);
    bf16* wvTlo = (bf16*)sym_addr(g_wvTlo);
    bf16* woThi = (bf16*)sym_addr(g_woThi);
    bf16* woTlo = (bf16*)sym_addr(g_woTlo);
    bf16* qhi   = (bf16*)sym_addr(g_qhi);
    bf16* qlo   = (bf16*)sym_addr(g_qlo);
    bf16* khi   = (bf16*)sym_addr(g_khi);
    bf16* klo   = (bf16*)sym_addr(g_klo);
    bf16* vthi  = (bf16*)sym_addr(g_vthi);
    bf16* vtlo  = (bf16*)sym_addr(g_vtlo);
    bf16* phi   = (bf16*)sym_addr(g_phi);
    bf16* plo   = (bf16*)sym_addr(g_plo);
    bf16* chi   = (bf16*)sym_addr(g_chi);
    bf16* clo   = (bf16*)sym_addr(g_clo);

    // smem: 4 stages x (2*A_TILE + 2*B_TILE) bf16
    const int smem128 = 4 * (2 * 128 * 24 + 2 * 128 * 24) * 2;  // 98304
    const int smem64  = 4 * (2 * 128 * 24 + 2 *  64 * 24) * 2;  // 73728
    cudaFuncSetAttribute(mma_gemm<4>, cudaFuncAttributeMaxDynamicSharedMemorySize, smem128);
    cudaFuncSetAttribute(mma_gemm<2>, cudaFuncAttributeMaxDynamicSharedMemorySize, smem64);

    const long long SS  = (long long)S_ * S_;
    const long long nSH = (long long)S_ * H_;

    // ---- prep: ordered so launch #3 (ncu capture slot) is the Q-proj GEMM ----
    split_kernel<<<(unsigned)((nSH / 4 + 255) / 256), 256>>>(             // #0
        (const float4*)x, (uint2*)xhi, (uint2*)xlo, nSH / 4);
    tsplit_kernel<<<dim3(H_ / 32,  H_ / 32), dim3(32, 8)>>>(wq, wqThi, wqTlo, H_, H_);   // #1
    tsplit_kernel<<<dim3(DH_ / 32, H_ / 32), dim3(32, 8)>>>(wk, wkThi, wkTlo, H_, DH_);  // #2

    // ---- Q-proj GEMM at launch #3 (profiled) ----
    mma_gemm<4><<<dim3(H_ / 128, S_ / 128, 1), 256, smem128>>>(            // #3
        xhi, xlo, wqThi, wqTlo, Qf, nullptr, nullptr, H_, H_, H_, H_, 0, 0, 0, 0);

    tsplit_kernel<<<dim3(DH_ / 32, H_ / 32), dim3(32, 8)>>>(wv, wvThi, wvTlo, H_, DH_);  // #4
    {
        const long long bS = (long long)(wvThi - wkThi);
        const long long cS = (long long)(Vf - Kf);
        mma_gemm<2><<<dim3(DH_ / 64, S_ / 128, 2), 256, smem64>>>(
            xhi, xlo, wkThi, wkTlo, Kf, nullptr, nullptr, H_, H_, H_, DH_, 0, bS, cS, 0);
    }

    // ---- RoPE -> bf16 hi/lo ----
    rope_split_kernel<<<(unsigned)(((long long)S_ * NH_ * 32 + 255) / 256), 256>>>(
        Qf, qhi, qlo, pos, NH_, H_);
    rope_split_kernel<<<(unsigned)(((long long)S_ * 32 + 255) / 256), 256>>>(
        Kf, khi, klo, pos, 1, DH_);

    // ---- V transpose + split ----
    tsplit_kernel<<<dim3(DH_ / 32, S_ / 32), dim3(32, 8)>>>(Vf, vthi, vtlo, S_, DH_);

    // ---- scores: attn_h = Q_h @ K^T, causal tile skip ----
    mma_gemm<4><<<dim3(S_ / 128, S_ / 128, NH_), 256, smem128>>>(
        qhi, qlo, khi, klo, attn, nullptr, nullptr, DH_, H_, DH_, S_, DH_, 0, SS, 1);

    // ---- softmax (analytic causal mask, prefix reads) ----
    softmax_kernel<<<dim3(S_, NH_), 256>>>(attn, phi, plo);

    // ---- ctx_h = P_h @ V, causal K-limit, fused bf16 split epilogue ----
    mma_gemm<4><<<dim3(DH_ / 128, S_ / 128, NH_), 256, smem128>>>(
        phi, plo, vthi, vtlo, nullptr, chi, clo, S_, S_, S_, H_, SS, 0, DH_, 2);

    // ---- wo transpose, then out = ctx @ w_o ----
    tsplit_kernel<<<dim3(H_ / 32, H_ / 32), dim3(32, 8)>>>(wo, woThi, woTlo, H_, H_);
    mma_gemm<4><<<dim3(H_ / 128, S_ / 128, 1), 256, smem128>>>(
        chi, clo, woThi, woTlo, out, nullptr, nullptr, H_, H_, H_, H_, 0, 0, 0, 0);
}

// round 10
// speedup vs baseline: 1.2980x; 1.2980x over previous
#include <cuda_runtime.h>
#include <cuda_fp16.h>
#include <cstdint>
#include <math.h>

// Problem constants
#define B_  1
#define S_  2048
#define H_  2048
#define NH_ 8
#define DH_ 256
#define SCALE_ 0.0625f   // 256^-0.5
#define NEG_  -1000000000.0f

typedef __half fp16;

// ================= helpers =====================================================
__device__ __forceinline__ uint32_t smem_to_u32(const void* smem_ptr) {
    uint32_t addr;
    asm("{ .reg .u64 tmp; cvta.to.shared.u64 tmp, %1; cvt.u32.u64 %0, tmp; }"
        : "=r"(addr) : "l"(smem_ptr));
    return addr;
}

__device__ __forceinline__ void cp_async16(uint32_t dst, const void* src) {
    asm volatile("cp.async.cg.shared.global [%0], [%1], 16;\n"
                 :: "r"(dst), "l"(src) : "memory");
}

__device__ __forceinline__ void ldsm_x4(uint32_t r[4], uint32_t addr) {
    asm volatile("ldmatrix.sync.aligned.m8n8.x4.shared.b16 {%0,%1,%2,%3}, [%4];"
                 : "=r"(r[0]), "=r"(r[1]), "=r"(r[2]), "=r"(r[3]) : "r"(addr));
}

__device__ __forceinline__ void mma_fp16(float acc[4], const uint32_t a[4], const uint32_t b[2]) {
    asm volatile(
        "mma.sync.aligned.m16n8k16.row.col.f32.f16.f16.f32 "
        "{%0,%1,%2,%3}, {%4,%5,%6,%7}, {%8,%9}, {%0,%1,%2,%3};"
        : "+f"(acc[0]), "+f"(acc[1]), "+f"(acc[2]), "+f"(acc[3])
        : "r"(a[0]), "r"(a[1]), "r"(a[2]), "r"(a[3]), "r"(b[0]), "r"(b[1]));
}

__device__ __forceinline__ uint32_t pack_h2(float v0, float v1) {
    fp16 h0 = __float2half(v0);
    fp16 h1 = __float2half(v1);
    return (uint32_t)__half_as_ushort(h0) | ((uint32_t)__half_as_ushort(h1) << 16);
}
__device__ __forceinline__ uint32_t pack_l2(float v0, float v1) {
    fp16 h0 = __float2half(v0);
    fp16 h1 = __float2half(v1);
    fp16 l0 = __float2half(v0 - __half2float(h0));
    fp16 l1 = __float2half(v1 - __half2float(h1));
    return (uint32_t)__half_as_ushort(l0) | ((uint32_t)__half_as_ushort(l1) << 16);
}
__device__ __forceinline__ uint2 pack_h4(float a, float b, float c, float d) {
    return make_uint2(pack_h2(a, b), pack_h2(c, d));
}
__device__ __forceinline__ uint2 pack_l4(float a, float b, float c, float d) {
    return make_uint2(pack_l2(a, b), pack_l2(c, d));
}

// ================= scratch (device globals; no allocation) ====================
__device__ __align__(128) float g_Q  [S_ * H_];
__device__ __align__(128) float g_K  [S_ * DH_];
__device__ __align__(128) float g_V  [S_ * DH_];

__device__ __align__(128) fp16 g_xh  [S_ * H_];            // x single fp16
__device__ __align__(128) fp16 g_wqThi[H_ * H_];
__device__ __align__(128) fp16 g_wqTlo[H_ * H_];
__device__ __align__(128) fp16 g_wkThi[DH_ * H_];
__device__ __align__(128) fp16 g_wkTlo[DH_ * H_];
__device__ __align__(128) fp16 g_wvThi[DH_ * H_];
__device__ __align__(128) fp16 g_wvTlo[DH_ * H_];
__device__ __align__(128) fp16 g_woThi[H_ * H_];
__device__ __align__(128) fp16 g_woTlo[H_ * H_];
__device__ __align__(128) fp16 g_qhi [S_ * H_];
__device__ __align__(128) fp16 g_qlo [S_ * H_];
__device__ __align__(128) fp16 g_khi [S_ * DH_];
__device__ __align__(128) fp16 g_klo [S_ * DH_];
__device__ __align__(128) fp16 g_vthi[DH_ * S_];
__device__ __align__(128) fp16 g_vtlo[DH_ * S_];
__device__ __align__(128) fp16 g_ph  [(long long)NH_ * S_ * S_];   // P single fp16
__device__ __align__(128) fp16 g_ch  [S_ * H_];                    // ctx single fp16

// ================= split-fp16 mma.sync GEMM, 4-stage pipeline ==================
// ASPLIT=true : 3-pass  (Ahi+Alo)@(Bhi+Blo) ~ hh+hl+lh   (QK only)
// ASPLIT=false: 2-pass  A@(Bhi+Blo)                       (A single fp16)
// A: M x K (K-major, lda); B: N x K (K-major, ldb).
// Output: fp32 C (ldc) or fp16-single Ch (ldc).
// mode bit0: causal tile skip; bit1: causal K limit.
template<int NT8, bool ASPLIT>
__global__ __launch_bounds__(256, 2)
void mma_gemm(const fp16* __restrict__ Ahi, const fp16* __restrict__ Alo,
              const fp16* __restrict__ Bhi, const fp16* __restrict__ Blo,
              float* __restrict__ C, fp16* __restrict__ Ch,
              int K, int lda, int ldb, int ldc,
              long long aStride, long long bStride, long long cStride,
              int mode)
{
    constexpr int TN     = NT8 * 32;
    constexpr int ROW    = 24;                 // fp16 per smem row (48B, conflict-free)
    constexpr int A_TILE = 128 * ROW;          // elems (one A operand tile)
    constexpr int B_TILE = TN * ROW;
    constexpr int NA     = ASPLIT ? 2 : 1;
    constexpr int STAGE  = NA * A_TILE + 2 * B_TILE;

    const int rowBase = blockIdx.y * 128;
    const int colBase = blockIdx.x * TN;

    if ((mode & 1) && colBase > rowBase + 127) return;

    int Keff = K;
    if (mode & 2) Keff = min(K, rowBase + 128);

    extern __shared__ fp16 smem[];
    const uint32_t sbase = smem_to_u32(smem);

    const int tid  = threadIdx.x;
    const int wid  = tid >> 5;
    const int lane = tid & 31;
    const int wm   = wid & 1;
    const int wn   = wid >> 1;

    Ahi += (long long)blockIdx.z * aStride;
    if (ASPLIT) Alo += (long long)blockIdx.z * aStride;
    Bhi += (long long)blockIdx.z * bStride;
    Blo += (long long)blockIdx.z * bStride;

    float acc[4][NT8][4] = {};

    const int nStages = Keff >> 4;             // K-chunk = 16

    const int lrow = tid >> 1;                 // 0..127
    const int lch  = tid & 1;

    auto issue = [&](int s) {
        const uint32_t sb = sbase + (uint32_t)(s & 3) * STAGE * 2;
        const int kt = s << 4;
        {
            const long long g = (long long)(rowBase + lrow) * lda + kt + lch * 8;
            const uint32_t d = sb + (uint32_t)(lrow * ROW + lch * 8) * 2;
            cp_async16(d, Ahi + g);
            if (ASPLIT) cp_async16(d + A_TILE * 2, Alo + g);
        }
        if (TN == 128 || tid < 128) {
            const long long g = (long long)(colBase + lrow) * ldb + kt + lch * 8;
            const uint32_t d = sb + (uint32_t)(NA * A_TILE + lrow * ROW + lch * 8) * 2;
            cp_async16(d,              Bhi + g);
            cp_async16(d + B_TILE * 2, Blo + g);
        }
        asm volatile("cp.async.commit_group;\n" ::: "memory");
    };

    issue(0);
    if (1 < nStages) issue(1);
    if (2 < nStages) issue(2);

    for (int s = 0; s < nStages; s++) {
        const int remain = nStages - 1 - s;
        if (remain >= 2)      asm volatile("cp.async.wait_group 2;\n" ::: "memory");
        else if (remain == 1) asm volatile("cp.async.wait_group 1;\n" ::: "memory");
        else                  asm volatile("cp.async.wait_group 0;\n" ::: "memory");
        __syncthreads();

        const uint32_t sb = sbase + (uint32_t)(s & 3) * STAGE * 2;
        const uint32_t sA = sb;
        const uint32_t sB = sb + NA * A_TILE * 2;

        // ---- B fragments: ldmatrix.x4 covers 2 nt tiles x 2 k-halves ----
        uint32_t bh[NT8][2], bl[NT8][2];
        {
            const int brow4 = wn * (NT8 * 8) + ((lane >> 4) << 3) + (lane & 7);
            const int bcol4 = (((lane >> 3) & 1) << 3);
            #pragma unroll
            for (int ntp = 0; ntp < NT8 / 2; ntp++) {
                const uint32_t addr =
                    sB + (uint32_t)((brow4 + ntp * 16) * ROW + bcol4) * 2;
                uint32_t rh[4], rl[4];
                ldsm_x4(rh, addr);
                ldsm_x4(rl, addr + B_TILE * 2);
                bh[2 * ntp][0] = rh[0]; bh[2 * ntp][1] = rh[1];
                bh[2 * ntp + 1][0] = rh[2]; bh[2 * ntp + 1][1] = rh[3];
                bl[2 * ntp][0] = rl[0]; bl[2 * ntp][1] = rl[1];
                bl[2 * ntp + 1][0] = rl[2]; bl[2 * ntp + 1][1] = rl[3];
            }
        }
        // ---- per-mt A fragments + MMA ----
        const int arow = wm * 64 + (lane & 15);
        const int acol = ((lane >> 4) << 3);
        #pragma unroll
        for (int mt = 0; mt < 4; mt++) {
            const uint32_t addr = sA + (uint32_t)((arow + mt * 16) * ROW + acol) * 2;
            uint32_t ah[4];
            ldsm_x4(ah, addr);
            if (ASPLIT) {
                uint32_t al[4];
                ldsm_x4(al, addr + A_TILE * 2);
                #pragma unroll
                for (int nt = 0; nt < NT8; nt++) {
                    mma_fp16(acc[mt][nt], ah, bh[nt]);
                    mma_fp16(acc[mt][nt], ah, bl[nt]);
                    mma_fp16(acc[mt][nt], al, bh[nt]);
                }
            } else {
                #pragma unroll
                for (int nt = 0; nt < NT8; nt++) {
                    mma_fp16(acc[mt][nt], ah, bh[nt]);
                    mma_fp16(acc[mt][nt], ah, bl[nt]);
                }
            }
        }

        if (s + 3 < nStages) issue(s + 3);
    }

    const int erow0 = rowBase + wm * 64 + (lane >> 2);
    const int ecol0 = colBase + wn * (NT8 * 8) + (lane & 3) * 2;
    #pragma unroll
    for (int mt = 0; mt < 4; mt++) {
        #pragma unroll
        for (int nt = 0; nt < NT8; nt++) {
            const int r = erow0 + mt * 16;
            const int c = ecol0 + nt * 8;
            if (C) {
                float* Cb = C + (long long)blockIdx.z * cStride;
                *(float2*)&Cb[(long long)r * ldc + c] =
                    make_float2(acc[mt][nt][0], acc[mt][nt][1]);
                *(float2*)&Cb[(long long)(r + 8) * ldc + c] =
                    make_float2(acc[mt][nt][2], acc[mt][nt][3]);
            }
            if (Ch) {
                fp16* Hb = Ch + (long long)blockIdx.z * cStride;
                *(uint32_t*)&Hb[(long long)r * ldc + c] = pack_h2(acc[mt][nt][0], acc[mt][nt][1]);
                *(uint32_t*)&Hb[(long long)(r + 8) * ldc + c] = pack_h2(acc[mt][nt][2], acc[mt][nt][3]);
            }
        }
    }
}

// ================= fp32 -> fp16 single convert (float4 vectorized) ============
__global__ void convert_kernel(const float4* __restrict__ in,
                               uint2* __restrict__ h, long long n4)
{
    long long i = (long long)blockIdx.x * blockDim.x + threadIdx.x;
    if (i >= n4) return;
    float4 v = in[i];
    h[i] = pack_h4(v.x, v.y, v.z, v.w);
}

// transpose + split: in[R][C] fp32 -> hiT/loT [C][R] fp16 (vectorized)
__global__ void tsplit_kernel(const float* __restrict__ in,
                              fp16* __restrict__ hiT, fp16* __restrict__ loT,
                              int R, int C)
{
    __shared__ float tile[32][36];
    const int c0 = blockIdx.x * 32;
    const int r0 = blockIdx.y * 32;
    const int tx = threadIdx.x;
    const int ty = threadIdx.y;

    {
        float4 v = *(const float4*)&in[(long long)(r0 + tx) * C + c0 + ty * 4];
        *(float4*)&tile[tx][ty * 4] = v;
    }
    __syncthreads();
    {
        float a = tile[ty * 4 + 0][tx];
        float b = tile[ty * 4 + 1][tx];
        float c = tile[ty * 4 + 2][tx];
        float d = tile[ty * 4 + 3][tx];
        const long long o = (long long)(c0 + tx) * R + r0 + ty * 4;
        *(uint2*)&hiT[o] = pack_h4(a, b, c, d);
        *(uint2*)&loT[o] = pack_l4(a, b, c, d);
    }
}

// ================= RoPE (fp32 in -> fp16 hi/lo out) ============================
__global__ void rope_split_kernel(const float* __restrict__ src,
                                  fp16* __restrict__ hi, fp16* __restrict__ lo,
                                  const int* __restrict__ pos,
                                  int nHeads, int rowStride)
{
    long long idx = (long long)blockIdx.x * blockDim.x + threadIdx.x;
    const long long total = (long long)S_ * nHeads * 32;
    if (idx >= total) return;
    const int d4 = (int)(idx & 31) * 4;
    const int h  = (int)((idx >> 5) % nHeads);
    const int s  = (int)(idx / (32LL * nHeads));

    const float p = (float)pos[s];
    const long long base = (long long)s * rowStride + h * DH_;

    float4 a = *(const float4*)&src[base + d4];
    float4 b = *(const float4*)&src[base + d4 + 128];

    float ra[4], rb[4];
    const float av[4] = {a.x, a.y, a.z, a.w};
    const float bv[4] = {b.x, b.y, b.z, b.w};
    #pragma unroll
    for (int k = 0; k < 4; k++) {
        const int d = d4 + k;
        float inv = exp2f(-((float)(2 * d) / (float)DH_) * log2f(10000.0f));
        float ang = p * inv;
        float sn, cs;
        sincosf(ang, &sn, &cs);
        ra[k] = av[k] * cs - bv[k] * sn;
        rb[k] = bv[k] * cs + av[k] * sn;
    }

    *(uint2*)&hi[base + d4]       = pack_h4(ra[0], ra[1], ra[2], ra[3]);
    *(uint2*)&lo[base + d4]       = pack_l4(ra[0], ra[1], ra[2], ra[3]);
    *(uint2*)&hi[base + d4 + 128] = pack_h4(rb[0], rb[1], rb[2], rb[3]);
    *(uint2*)&lo[base + d4 + 128] = pack_l4(rb[0], rb[1], rb[2], rb[3]);
}

// ================= causal scale + softmax (fp32 out + single fp16 P) ==========
__global__ void softmax_kernel(float* __restrict__ attn, fp16* __restrict__ ph)
{
    const int i = blockIdx.x;
    const int h = blockIdx.y;
    const long long rowOff = ((long long)h * S_ + i) * S_;
    float* row = attn + rowOff;
    const int t = threadIdx.x;
    const int lane = t & 31, warp = t >> 5;

    const int kLimit = ((i >> 7) + 1) << 7;

    float vals[8];
    float mx = -INFINITY;
    #pragma unroll
    for (int j = 0; j < 2; j++) {
        const int col4 = 4 * t + j * 1024;
        if (col4 <= i) {
            float4 v = *(const float4*)&row[col4];
            const float vv[4] = {v.x, v.y, v.z, v.w};
            #pragma unroll
            for (int k = 0; k < 4; k++) {
                const int col = col4 + k;
                float u = (col <= i) ? fmaf(vv[k], SCALE_, 0.0f) : NEG_;
                vals[j * 4 + k] = u;
                mx = fmaxf(mx, u);
            }
        } else {
            #pragma unroll
            for (int k = 0; k < 4; k++) vals[j * 4 + k] = NEG_;
        }
    }

    __shared__ float red[8];
    #pragma unroll
    for (int o = 16; o > 0; o >>= 1)
        mx = fmaxf(mx, __shfl_xor_sync(0xffffffffu, mx, o));
    if (lane == 0) red[warp] = mx;
    __syncthreads();
    {
        float m = red[lane & 7];
        #pragma unroll
        for (int o = 4; o > 0; o >>= 1)
            m = fmaxf(m, __shfl_xor_sync(0xffffffffu, m, o));
        mx = m;
    }

    float sum = 0.0f;
    #pragma unroll
    for (int j = 0; j < 8; j++) {
        vals[j] = __expf(vals[j] - mx);
        sum += vals[j];
    }
    #pragma unroll
    for (int o = 16; o > 0; o >>= 1)
        sum += __shfl_xor_sync(0xffffffffu, sum, o);
    __syncthreads();
    if (lane == 0) red[warp] = sum;
    __syncthreads();
    {
        float m = red[lane & 7];
        #pragma unroll
        for (int o = 4; o > 0; o >>= 1)
            m += __shfl_xor_sync(0xffffffffu, m, o);
        sum = m;
    }

    const float inv = 1.0f / sum;
    #pragma unroll
    for (int j = 0; j < 2; j++) {
        const int col4 = 4 * t + j * 1024;
        float p0 = vals[j * 4 + 0] * inv;
        float p1 = vals[j * 4 + 1] * inv;
        float p2 = vals[j * 4 + 2] * inv;
        float p3 = vals[j * 4 + 3] * inv;
        *(float4*)&row[col4] = make_float4(p0, p1, p2, p3);
        if (col4 < kLimit)
            *(uint2*)&ph[rowOff + col4] = pack_h4(p0, p1, p2, p3);
    }
}

// ================= launch ======================================================
static void* sym_addr(const void* sym)
{
    void* p = nullptr;
    cudaGetSymbolAddress(&p, sym);
    return p;
}

extern "C" void kernel_launch(void* const* d_in, const int* in_sizes, int n_in,
                              void* d_out, int out_size)
{
    const float* x    = (const float*)d_in[0];
    const int*   pos  = (const int*)  d_in[1];
    const float* wq   = (const float*)d_in[3];
    const float* wk   = (const float*)d_in[4];
    const float* wv   = (const float*)d_in[5];
    const float* wo   = (const float*)d_in[6];

    float* out  = (float*)d_out;
    float* attn = out + (long long)B_ * S_ * H_;

    float* Qf = (float*)sym_addr(g_Q);
    float* Kf = (float*)sym_addr(g_K);
    float* Vf = (float*)sym_addr(g_V);

    fp16* xh    = (fp16*)sym_addr(g_xh);
    fp16* wqThi = (fp16*)sym_addr(g_wqThi);
    fp16* wqTlo = (fp16*)sym_addr(g_wqTlo);
    fp16* wkThi = (fp16*)sym_addr(g_wkThi);
    fp16* wkTlo = (fp16*)sym_addr(g_wkTlo);
    fp16* wvThi = (fp16*)sym_addr(g_wvThi);
    fp16* wvTlo = (fp16*)sym_addr(g_wvTlo);
    fp16* woThi = (fp16*)sym_addr(g_woThi);
    fp16* woTlo = (fp16*)sym_addr(g_woTlo);
    fp16* qhi   = (fp16*)sym_addr(g_qhi);
    fp16* qlo   = (fp16*)sym_addr(g_qlo);
    fp16* khi   = (fp16*)sym_addr(g_khi);
    fp16* klo   = (fp16*)sym_addr(g_klo);
    fp16* vthi  = (fp16*)sym_addr(g_vthi);
    fp16* vtlo  = (fp16*)sym_addr(g_vtlo);
    fp16* ph    = (fp16*)sym_addr(g_ph);
    fp16* ch    = (fp16*)sym_addr(g_ch);

    // smem: 4 stages
    const int smem2p128 = 4 * (1 * 128 * 24 + 2 * 128 * 24) * 2;  // 73728 (2-pass, TN=128)
    const int smem2p64  = 4 * (1 * 128 * 24 + 2 *  64 * 24) * 2;  // 49152 (2-pass, TN=64)
    const int smem3p128 = 4 * (2 * 128 * 24 + 2 * 128 * 24) * 2;  // 98304 (3-pass, TN=128)
    cudaFuncSetAttribute(mma_gemm<4,false>, cudaFuncAttributeMaxDynamicSharedMemorySize, smem2p128);
    cudaFuncSetAttribute(mma_gemm<2,false>, cudaFuncAttributeMaxDynamicSharedMemorySize, smem2p64);
    cudaFuncSetAttribute(mma_gemm<4,true>,  cudaFuncAttributeMaxDynamicSharedMemorySize, smem3p128);

    const long long SS  = (long long)S_ * S_;
    const long long nSH = (long long)S_ * H_;

    // ---- prep: Q-proj GEMM stays at launch #3 for ncu capture ----
    convert_kernel<<<(unsigned)((nSH / 4 + 255) / 256), 256>>>(           // #0
        (const float4*)x, (uint2*)xh, nSH / 4);
    tsplit_kernel<<<dim3(H_ / 32,  H_ / 32), dim3(32, 8)>>>(wq, wqThi, wqTlo, H_, H_);   // #1
    tsplit_kernel<<<dim3(DH_ / 32, H_ / 32), dim3(32, 8)>>>(wk, wkThi, wkTlo, H_, DH_);  // #2

    // ---- Q-proj (2-pass): launch #3 ----
    mma_gemm<4,false><<<dim3(H_ / 128, S_ / 128, 1), 256, smem2p128>>>(
        xh, nullptr, wqThi, wqTlo, Qf, nullptr, H_, H_, H_, H_, 0, 0, 0, 0);

    tsplit_kernel<<<dim3(DH_ / 32, H_ / 32), dim3(32, 8)>>>(wv, wvThi, wvTlo, H_, DH_);
    {
        const long long bS = (long long)(wvThi - wkThi);
        const long long cS = (long long)(Vf - Kf);
        mma_gemm<2,false><<<dim3(DH_ / 64, S_ / 128, 2), 256, smem2p64>>>(
            xh, nullptr, wkThi, wkTlo, Kf, nullptr, H_, H_, H_, DH_, 0, bS, cS, 0);
    }

    // ---- RoPE -> fp16 hi/lo (for 3-pass QK) ----
    rope_split_kernel<<<(unsigned)(((long long)S_ * NH_ * 32 + 255) / 256), 256>>>(
        Qf, qhi, qlo, pos, NH_, H_);
    rope_split_kernel<<<(unsigned)(((long long)S_ * 32 + 255) / 256), 256>>>(
        Kf, khi, klo, pos, 1, DH_);

    // ---- V transpose + split ----
    tsplit_kernel<<<dim3(DH_ / 32, S_ / 32), dim3(32, 8)>>>(Vf, vthi, vtlo, S_, DH_);

    // ---- scores: attn_h = Q_h @ K^T (3-pass, causal tile skip) ----
    mma_gemm<4,true><<<dim3(S_ / 128, S_ / 128, NH_), 256, smem3p128>>>(
        qhi, qlo, khi, klo, attn, nullptr, DH_, H_, DH_, S_, DH_, 0, SS, 1);

    // ---- softmax (analytic causal mask, single fp16 P) ----
    softmax_kernel<<<dim3(S_, NH_), 256>>>(attn, ph);

    // ---- ctx_h = P_h @ V (2-pass, causal K-limit, fp16 ctx epilogue) ----
    mma_gemm<4,false><<<dim3(DH_ / 128, S_ / 128, NH_), 256, smem2p128>>>(
        ph, nullptr, vthi, vtlo, nullptr, ch, S_, S_, S_, H_, SS, 0, DH_, 2);

    // ---- wo transpose, then out = ctx @ w_o (2-pass) ----
    tsplit_kernel<<<dim3(H_ / 32, H_ / 32), dim3(32, 8)>>>(wo, woThi, woTlo, H_, H_);
    mma_gemm<4,false><<<dim3(H_ / 128, S_ / 128, 1), 256, smem2p128>>>(
        ch, nullptr, woThi, woTlo, out, nullptr, H_, H_, H_, H_, 0, 0, 0, 0);
}

// round 11
// speedup vs baseline: 1.3439x; 1.0354x over previous
#include <cuda_runtime.h>
#include <cuda_fp16.h>
#include <cstdint>
#include <math.h>

// Problem constants
#define B_  1
#define S_  2048
#define H_  2048
#define NH_ 8
#define DH_ 256
#define SCALE_ 0.0625f   // 256^-0.5
#define NEG_  -1000000000.0f

typedef __half fp16;

// ================= helpers =====================================================
__device__ __forceinline__ uint32_t smem_to_u32(const void* smem_ptr) {
    uint32_t addr;
    asm("{ .reg .u64 tmp; cvta.to.shared.u64 tmp, %1; cvt.u32.u64 %0, tmp; }"
        : "=r"(addr) : "l"(smem_ptr));
    return addr;
}

__device__ __forceinline__ void cp_async16(uint32_t dst, const void* src) {
    asm volatile("cp.async.cg.shared.global [%0], [%1], 16;\n"
                 :: "r"(dst), "l"(src) : "memory");
}

__device__ __forceinline__ void ldsm_x4(uint32_t r[4], uint32_t addr) {
    asm volatile("ldmatrix.sync.aligned.m8n8.x4.shared.b16 {%0,%1,%2,%3}, [%4];"
                 : "=r"(r[0]), "=r"(r[1]), "=r"(r[2]), "=r"(r[3]) : "r"(addr));
}

__device__ __forceinline__ void mma_fp16(float acc[4], const uint32_t a[4], const uint32_t b[2]) {
    asm volatile(
        "mma.sync.aligned.m16n8k16.row.col.f32.f16.f16.f32 "
        "{%0,%1,%2,%3}, {%4,%5,%6,%7}, {%8,%9}, {%0,%1,%2,%3};"
        : "+f"(acc[0]), "+f"(acc[1]), "+f"(acc[2]), "+f"(acc[3])
        : "r"(a[0]), "r"(a[1]), "r"(a[2]), "r"(a[3]), "r"(b[0]), "r"(b[1]));
}

__device__ __forceinline__ uint32_t pack_h2(float v0, float v1) {
    fp16 h0 = __float2half(v0);
    fp16 h1 = __float2half(v1);
    return (uint32_t)__half_as_ushort(h0) | ((uint32_t)__half_as_ushort(h1) << 16);
}
__device__ __forceinline__ uint32_t pack_l2(float v0, float v1) {
    fp16 h0 = __float2half(v0);
    fp16 h1 = __float2half(v1);
    fp16 l0 = __float2half(v0 - __half2float(h0));
    fp16 l1 = __float2half(v1 - __half2float(h1));
    return (uint32_t)__half_as_ushort(l0) | ((uint32_t)__half_as_ushort(l1) << 16);
}
__device__ __forceinline__ uint2 pack_h4(float a, float b, float c, float d) {
    return make_uint2(pack_h2(a, b), pack_h2(c, d));
}
__device__ __forceinline__ uint2 pack_l4(float a, float b, float c, float d) {
    return make_uint2(pack_l2(a, b), pack_l2(c, d));
}

// ================= scratch (device globals; no allocation) ====================
__device__ __align__(128) float g_Q  [S_ * H_];
__device__ __align__(128) float g_K  [S_ * DH_];
__device__ __align__(128) float g_V  [S_ * DH_];

__device__ __align__(128) fp16 g_xh  [S_ * H_];            // x single fp16
__device__ __align__(128) fp16 g_wqThi[H_ * H_];
__device__ __align__(128) fp16 g_wqTlo[H_ * H_];
__device__ __align__(128) fp16 g_wkThi[DH_ * H_];
__device__ __align__(128) fp16 g_wkTlo[DH_ * H_];
__device__ __align__(128) fp16 g_wvThi[DH_ * H_];
__device__ __align__(128) fp16 g_wvTlo[DH_ * H_];
__device__ __align__(128) fp16 g_woThi[H_ * H_];
__device__ __align__(128) fp16 g_woTlo[H_ * H_];
__device__ __align__(128) fp16 g_qhi [S_ * H_];
__device__ __align__(128) fp16 g_qlo [S_ * H_];
__device__ __align__(128) fp16 g_khi [S_ * DH_];
__device__ __align__(128) fp16 g_klo [S_ * DH_];
__device__ __align__(128) fp16 g_vthi[DH_ * S_];
__device__ __align__(128) fp16 g_vtlo[DH_ * S_];
__device__ __align__(128) fp16 g_ph  [(long long)NH_ * S_ * S_];   // P single fp16
__device__ __align__(128) fp16 g_ch  [S_ * H_];                    // ctx single fp16

// ================= split-fp16 mma.sync GEMM, 4-stage pipeline ==================
// ASPLIT=true : 3-pass  (Ahi+Alo)@(Bhi+Blo) ~ hh+hl+lh   (QK only)
// ASPLIT=false: 2-pass  A@(Bhi+Blo)  — pass-major MMA order (16 indep accs)
template<int NT8, bool ASPLIT>
__global__ __launch_bounds__(256, 2)
void mma_gemm(const fp16* __restrict__ Ahi, const fp16* __restrict__ Alo,
              const fp16* __restrict__ Bhi, const fp16* __restrict__ Blo,
              float* __restrict__ C, fp16* __restrict__ Ch,
              int K, int lda, int ldb, int ldc,
              long long aStride, long long bStride, long long cStride,
              int mode)
{
    constexpr int TN     = NT8 * 32;
    constexpr int ROW    = 24;                 // fp16 per smem row (48B, conflict-free)
    constexpr int A_TILE = 128 * ROW;
    constexpr int B_TILE = TN * ROW;
    constexpr int NA     = ASPLIT ? 2 : 1;
    constexpr int STAGE  = NA * A_TILE + 2 * B_TILE;

    const int rowBase = blockIdx.y * 128;
    const int colBase = blockIdx.x * TN;

    if ((mode & 1) && colBase > rowBase + 127) return;

    int Keff = K;
    if (mode & 2) Keff = min(K, rowBase + 128);

    extern __shared__ fp16 smem[];
    const uint32_t sbase = smem_to_u32(smem);

    const int tid  = threadIdx.x;
    const int wid  = tid >> 5;
    const int lane = tid & 31;
    const int wm   = wid & 1;
    const int wn   = wid >> 1;

    Ahi += (long long)blockIdx.z * aStride;
    if (ASPLIT) Alo += (long long)blockIdx.z * aStride;
    Bhi += (long long)blockIdx.z * bStride;
    Blo += (long long)blockIdx.z * bStride;

    float acc[4][NT8][4] = {};

    const int nStages = Keff >> 4;             // K-chunk = 16

    const int lrow = tid >> 1;
    const int lch  = tid & 1;

    auto issue = [&](int s) {
        const uint32_t sb = sbase + (uint32_t)(s & 3) * STAGE * 2;
        const int kt = s << 4;
        {
            const long long g = (long long)(rowBase + lrow) * lda + kt + lch * 8;
            const uint32_t d = sb + (uint32_t)(lrow * ROW + lch * 8) * 2;
            cp_async16(d, Ahi + g);
            if (ASPLIT) cp_async16(d + A_TILE * 2, Alo + g);
        }
        if (TN == 128 || tid < 128) {
            const long long g = (long long)(colBase + lrow) * ldb + kt + lch * 8;
            const uint32_t d = sb + (uint32_t)(NA * A_TILE + lrow * ROW + lch * 8) * 2;
            cp_async16(d,              Bhi + g);
            cp_async16(d + B_TILE * 2, Blo + g);
        }
        asm volatile("cp.async.commit_group;\n" ::: "memory");
    };

    issue(0);
    if (1 < nStages) issue(1);
    if (2 < nStages) issue(2);

    for (int s = 0; s < nStages; s++) {
        const int remain = nStages - 1 - s;
        if (remain >= 2)      asm volatile("cp.async.wait_group 2;\n" ::: "memory");
        else if (remain == 1) asm volatile("cp.async.wait_group 1;\n" ::: "memory");
        else                  asm volatile("cp.async.wait_group 0;\n" ::: "memory");
        __syncthreads();

        const uint32_t sb = sbase + (uint32_t)(s & 3) * STAGE * 2;
        const uint32_t sA = sb;
        const uint32_t sB = sb + NA * A_TILE * 2;

        // ---- B fragments: ldmatrix.x4 covers 2 nt tiles x 2 k-halves ----
        uint32_t bh[NT8][2], bl[NT8][2];
        {
            const int brow4 = wn * (NT8 * 8) + ((lane >> 4) << 3) + (lane & 7);
            const int bcol4 = (((lane >> 3) & 1) << 3);
            #pragma unroll
            for (int ntp = 0; ntp < NT8 / 2; ntp++) {
                const uint32_t addr =
                    sB + (uint32_t)((brow4 + ntp * 16) * ROW + bcol4) * 2;
                uint32_t rh[4], rl[4];
                ldsm_x4(rh, addr);
                ldsm_x4(rl, addr + B_TILE * 2);
                bh[2 * ntp][0] = rh[0]; bh[2 * ntp][1] = rh[1];
                bh[2 * ntp + 1][0] = rh[2]; bh[2 * ntp + 1][1] = rh[3];
                bl[2 * ntp][0] = rl[0]; bl[2 * ntp][1] = rl[1];
                bl[2 * ntp + 1][0] = rl[2]; bl[2 * ntp + 1][1] = rl[3];
            }
        }

        const int arow = wm * 64 + (lane & 15);
        const int acol = ((lane >> 4) << 3);

        if (!ASPLIT) {
            // ---- 2-pass, pass-major: 16 independent accumulators per pass ----
            uint32_t ah[4][4];
            #pragma unroll
            for (int mt = 0; mt < 4; mt++) {
                const uint32_t addr = sA + (uint32_t)((arow + mt * 16) * ROW + acol) * 2;
                ldsm_x4(ah[mt], addr);
            }
            #pragma unroll
            for (int mt = 0; mt < 4; mt++)
                #pragma unroll
                for (int nt = 0; nt < NT8; nt++)
                    mma_fp16(acc[mt][nt], ah[mt], bh[nt]);
            #pragma unroll
            for (int mt = 0; mt < 4; mt++)
                #pragma unroll
                for (int nt = 0; nt < NT8; nt++)
                    mma_fp16(acc[mt][nt], ah[mt], bl[nt]);
        } else {
            // ---- 3-pass, pass-major within mt: 4 independent accs per pass ----
            #pragma unroll
            for (int mt = 0; mt < 4; mt++) {
                const uint32_t addr = sA + (uint32_t)((arow + mt * 16) * ROW + acol) * 2;
                uint32_t ah[4], al[4];
                ldsm_x4(ah, addr);
                ldsm_x4(al, addr + A_TILE * 2);
                #pragma unroll
                for (int nt = 0; nt < NT8; nt++)
                    mma_fp16(acc[mt][nt], ah, bh[nt]);
                #pragma unroll
                for (int nt = 0; nt < NT8; nt++)
                    mma_fp16(acc[mt][nt], ah, bl[nt]);
                #pragma unroll
                for (int nt = 0; nt < NT8; nt++)
                    mma_fp16(acc[mt][nt], al, bh[nt]);
            }
        }

        if (s + 3 < nStages) issue(s + 3);
    }

    const int erow0 = rowBase + wm * 64 + (lane >> 2);
    const int ecol0 = colBase + wn * (NT8 * 8) + (lane & 3) * 2;
    #pragma unroll
    for (int mt = 0; mt < 4; mt++) {
        #pragma unroll
        for (int nt = 0; nt < NT8; nt++) {
            const int r = erow0 + mt * 16;
            const int c = ecol0 + nt * 8;
            if (C) {
                float* Cb = C + (long long)blockIdx.z * cStride;
                *(float2*)&Cb[(long long)r * ldc + c] =
                    make_float2(acc[mt][nt][0], acc[mt][nt][1]);
                *(float2*)&Cb[(long long)(r + 8) * ldc + c] =
                    make_float2(acc[mt][nt][2], acc[mt][nt][3]);
            }
            if (Ch) {
                fp16* Hb = Ch + (long long)blockIdx.z * cStride;
                *(uint32_t*)&Hb[(long long)r * ldc + c] = pack_h2(acc[mt][nt][0], acc[mt][nt][1]);
                *(uint32_t*)&Hb[(long long)(r + 8) * ldc + c] = pack_h2(acc[mt][nt][2], acc[mt][nt][3]);
            }
        }
    }
}

// ================= fp32 -> fp16 single convert (float4 vectorized) ============
__global__ void convert_kernel(const float4* __restrict__ in,
                               uint2* __restrict__ h, long long n4)
{
    long long i = (long long)blockIdx.x * blockDim.x + threadIdx.x;
    if (i >= n4) return;
    float4 v = in[i];
    h[i] = pack_h4(v.x, v.y, v.z, v.w);
}

// transpose + split: in[R][C] fp32 -> hiT/loT [C][R] fp16 (vectorized)
__global__ void tsplit_kernel(const float* __restrict__ in,
                              fp16* __restrict__ hiT, fp16* __restrict__ loT,
                              int R, int C)
{
    __shared__ float tile[32][36];
    const int c0 = blockIdx.x * 32;
    const int r0 = blockIdx.y * 32;
    const int tx = threadIdx.x;
    const int ty = threadIdx.y;

    {
        float4 v = *(const float4*)&in[(long long)(r0 + tx) * C + c0 + ty * 4];
        *(float4*)&tile[tx][ty * 4] = v;
    }
    __syncthreads();
    {
        float a = tile[ty * 4 + 0][tx];
        float b = tile[ty * 4 + 1][tx];
        float c = tile[ty * 4 + 2][tx];
        float d = tile[ty * 4 + 3][tx];
        const long long o = (long long)(c0 + tx) * R + r0 + ty * 4;
        *(uint2*)&hiT[o] = pack_h4(a, b, c, d);
        *(uint2*)&loT[o] = pack_l4(a, b, c, d);
    }
}

// ================= RoPE (fp32 in -> fp16 hi/lo out) ============================
__global__ void rope_split_kernel(const float* __restrict__ src,
                                  fp16* __restrict__ hi, fp16* __restrict__ lo,
                                  const int* __restrict__ pos,
                                  int nHeads, int rowStride)
{
    long long idx = (long long)blockIdx.x * blockDim.x + threadIdx.x;
    const long long total = (long long)S_ * nHeads * 32;
    if (idx >= total) return;
    const int d4 = (int)(idx & 31) * 4;
    const int h  = (int)((idx >> 5) % nHeads);
    const int s  = (int)(idx / (32LL * nHeads));

    const float p = (float)pos[s];
    const long long base = (long long)s * rowStride + h * DH_;

    float4 a = *(const float4*)&src[base + d4];
    float4 b = *(const float4*)&src[base + d4 + 128];

    float ra[4], rb[4];
    const float av[4] = {a.x, a.y, a.z, a.w};
    const float bv[4] = {b.x, b.y, b.z, b.w};
    #pragma unroll
    for (int k = 0; k < 4; k++) {
        const int d = d4 + k;
        float inv = exp2f(-((float)(2 * d) / (float)DH_) * log2f(10000.0f));
        float ang = p * inv;
        float sn, cs;
        sincosf(ang, &sn, &cs);
        ra[k] = av[k] * cs - bv[k] * sn;
        rb[k] = bv[k] * cs + av[k] * sn;
    }

    *(uint2*)&hi[base + d4]       = pack_h4(ra[0], ra[1], ra[2], ra[3]);
    *(uint2*)&lo[base + d4]       = pack_l4(ra[0], ra[1], ra[2], ra[3]);
    *(uint2*)&hi[base + d4 + 128] = pack_h4(rb[0], rb[1], rb[2], rb[3]);
    *(uint2*)&lo[base + d4 + 128] = pack_l4(rb[0], rb[1], rb[2], rb[3]);
}

// ================= causal scale + softmax (fp32 out + single fp16 P) ==========
__global__ void softmax_kernel(float* __restrict__ attn, fp16* __restrict__ ph)
{
    const int i = blockIdx.x;
    const int h = blockIdx.y;
    const long long rowOff = ((long long)h * S_ + i) * S_;
    float* row = attn + rowOff;
    const int t = threadIdx.x;
    const int lane = t & 31, warp = t >> 5;

    const int kLimit = ((i >> 7) + 1) << 7;

    float vals[8];
    float mx = -INFINITY;
    #pragma unroll
    for (int j = 0; j < 2; j++) {
        const int col4 = 4 * t + j * 1024;
        if (col4 <= i) {
            float4 v = *(const float4*)&row[col4];
            const float vv[4] = {v.x, v.y, v.z, v.w};
            #pragma unroll
            for (int k = 0; k < 4; k++) {
                const int col = col4 + k;
                float u = (col <= i) ? fmaf(vv[k], SCALE_, 0.0f) : NEG_;
                vals[j * 4 + k] = u;
                mx = fmaxf(mx, u);
            }
        } else {
            #pragma unroll
            for (int k = 0; k < 4; k++) vals[j * 4 + k] = NEG_;
        }
    }

    __shared__ float red[8];
    #pragma unroll
    for (int o = 16; o > 0; o >>= 1)
        mx = fmaxf(mx, __shfl_xor_sync(0xffffffffu, mx, o));
    if (lane == 0) red[warp] = mx;
    __syncthreads();
    {
        float m = red[lane & 7];
        #pragma unroll
        for (int o = 4; o > 0; o >>= 1)
            m = fmaxf(m, __shfl_xor_sync(0xffffffffu, m, o));
        mx = m;
    }

    float sum = 0.0f;
    #pragma unroll
    for (int j = 0; j < 8; j++) {
        vals[j] = __expf(vals[j] - mx);
        sum += vals[j];
    }
    #pragma unroll
    for (int o = 16; o > 0; o >>= 1)
        sum += __shfl_xor_sync(0xffffffffu, sum, o);
    __syncthreads();
    if (lane == 0) red[warp] = sum;
    __syncthreads();
    {
        float m = red[lane & 7];
        #pragma unroll
        for (int o = 4; o > 0; o >>= 1)
            m += __shfl_xor_sync(0xffffffffu, m, o);
        sum = m;
    }

    const float inv = 1.0f / sum;
    #pragma unroll
    for (int j = 0; j < 2; j++) {
        const int col4 = 4 * t + j * 1024;
        float p0 = vals[j * 4 + 0] * inv;
        float p1 = vals[j * 4 + 1] * inv;
        float p2 = vals[j * 4 + 2] * inv;
        float p3 = vals[j * 4 + 3] * inv;
        *(float4*)&row[col4] = make_float4(p0, p1, p2, p3);
        if (col4 < kLimit)
            *(uint2*)&ph[rowOff + col4] = pack_h4(p0, p1, p2, p3);
    }
}

// ================= launch ======================================================
static void* sym_addr(const void* sym)
{
    void* p = nullptr;
    cudaGetSymbolAddress(&p, sym);
    return p;
}

extern "C" void kernel_launch(void* const* d_in, const int* in_sizes, int n_in,
                              void* d_out, int out_size)
{
    const float* x    = (const float*)d_in[0];
    const int*   pos  = (const int*)  d_in[1];
    const float* wq   = (const float*)d_in[3];
    const float* wk   = (const float*)d_in[4];
    const float* wv   = (const float*)d_in[5];
    const float* wo   = (const float*)d_in[6];

    float* out  = (float*)d_out;
    float* attn = out + (long long)B_ * S_ * H_;

    float* Qf = (float*)sym_addr(g_Q);
    float* Kf = (float*)sym_addr(g_K);
    float* Vf = (float*)sym_addr(g_V);

    fp16* xh    = (fp16*)sym_addr(g_xh);
    fp16* wqThi = (fp16*)sym_addr(g_wqThi);
    fp16* wqTlo = (fp16*)sym_addr(g_wqTlo);
    fp16* wkThi = (fp16*)sym_addr(g_wkThi);
    fp16* wkTlo = (fp16*)sym_addr(g_wkTlo);
    fp16* wvThi = (fp16*)sym_addr(g_wvThi);
    fp16* wvTlo = (fp16*)sym_addr(g_wvTlo);
    fp16* woThi = (fp16*)sym_addr(g_woThi);
    fp16* woTlo = (fp16*)sym_addr(g_woTlo);
    fp16* qhi   = (fp16*)sym_addr(g_qhi);
    fp16* qlo   = (fp16*)sym_addr(g_qlo);
    fp16* khi   = (fp16*)sym_addr(g_khi);
    fp16* klo   = (fp16*)sym_addr(g_klo);
    fp16* vthi  = (fp16*)sym_addr(g_vthi);
    fp16* vtlo  = (fp16*)sym_addr(g_vtlo);
    fp16* ph    = (fp16*)sym_addr(g_ph);
    fp16* ch    = (fp16*)sym_addr(g_ch);

    const int smem2p128 = 4 * (1 * 128 * 24 + 2 * 128 * 24) * 2;  // 73728
    const int smem2p64  = 4 * (1 * 128 * 24 + 2 *  64 * 24) * 2;  // 49152
    const int smem3p128 = 4 * (2 * 128 * 24 + 2 * 128 * 24) * 2;  // 98304
    cudaFuncSetAttribute(mma_gemm<4,false>, cudaFuncAttributeMaxDynamicSharedMemorySize, smem2p128);
    cudaFuncSetAttribute(mma_gemm<2,false>, cudaFuncAttributeMaxDynamicSharedMemorySize, smem2p64);
    cudaFuncSetAttribute(mma_gemm<4,true>,  cudaFuncAttributeMaxDynamicSharedMemorySize, smem3p128);

    const long long SS  = (long long)S_ * S_;
    const long long nSH = (long long)S_ * H_;

    // ---- prep: Q-proj GEMM stays at launch #3 for ncu capture ----
    convert_kernel<<<(unsigned)((nSH / 4 + 255) / 256), 256>>>(
        (const float4*)x, (uint2*)xh, nSH / 4);
    tsplit_kernel<<<dim3(H_ / 32,  H_ / 32), dim3(32, 8)>>>(wq, wqThi, wqTlo, H_, H_);
    tsplit_kernel<<<dim3(DH_ / 32, H_ / 32), dim3(32, 8)>>>(wk, wkThi, wkTlo, H_, DH_);

    // ---- Q-proj (2-pass): launch #3 ----
    mma_gemm<4,false><<<dim3(H_ / 128, S_ / 128, 1), 256, smem2p128>>>(
        xh, nullptr, wqThi, wqTlo, Qf, nullptr, H_, H_, H_, H_, 0, 0, 0, 0);

    tsplit_kernel<<<dim3(DH_ / 32, H_ / 32), dim3(32, 8)>>>(wv, wvThi, wvTlo, H_, DH_);
    {
        const long long bS = (long long)(wvThi - wkThi);
        const long long cS = (long long)(Vf - Kf);
        mma_gemm<2,false><<<dim3(DH_ / 64, S_ / 128, 2), 256, smem2p64>>>(
            xh, nullptr, wkThi, wkTlo, Kf, nullptr, H_, H_, H_, DH_, 0, bS, cS, 0);
    }

    // ---- RoPE -> fp16 hi/lo (for 3-pass QK) ----
    rope_split_kernel<<<(unsigned)(((long long)S_ * NH_ * 32 + 255) / 256), 256>>>(
        Qf, qhi, qlo, pos, NH_, H_);
    rope_split_kernel<<<(unsigned)(((long long)S_ * 32 + 255) / 256), 256>>>(
        Kf, khi, klo, pos, 1, DH_);

    // ---- V transpose + split ----
    tsplit_kernel<<<dim3(DH_ / 32, S_ / 32), dim3(32, 8)>>>(Vf, vthi, vtlo, S_, DH_);

    // ---- scores: attn_h = Q_h @ K^T (3-pass, causal tile skip) ----
    mma_gemm<4,true><<<dim3(S_ / 128, S_ / 128, NH_), 256, smem3p128>>>(
        qhi, qlo, khi, klo, attn, nullptr, DH_, H_, DH_, S_, DH_, 0, SS, 1);

    // ---- softmax (analytic causal mask, single fp16 P) ----
    softmax_kernel<<<dim3(S_, NH_), 256>>>(attn, ph);

    // ---- ctx_h = P_h @ V (2-pass, causal K-limit, fp16 ctx epilogue) ----
    mma_gemm<4,false><<<dim3(DH_ / 128, S_ / 128, NH_), 256, smem2p128>>>(
        ph, nullptr, vthi, vtlo, nullptr, ch, S_, S_, S_, H_, SS, 0, DH_, 2);

    // ---- wo transpose, then out = ctx @ w_o (2-pass) ----
    tsplit_kernel<<<dim3(H_ / 32, H_ / 32), dim3(32, 8)>>>(wo, woThi, woTlo, H_, H_);
    mma_gemm<4,false><<<dim3(H_ / 128, S_ / 128, 1), 256, smem2p128>>>(
        ch, nullptr, woThi, woTlo, out, nullptr, H_, H_, H_, H_, 0, 0, 0, 0);
}

// round 12
// speedup vs baseline: 1.7636x; 1.3123x over previous
#include <cuda_runtime.h>
#include <cuda_fp16.h>
#include <cstdint>
#include <math.h>

// Problem constants
#define B_  1
#define S_  2048
#define H_  2048
#define NH_ 8
#define DH_ 256
#define SCALE_ 0.0625f   // 256^-0.5
#define NEG_  -1000000000.0f

typedef __half fp16;

// ================= helpers =====================================================
__device__ __forceinline__ uint32_t smem_to_u32(const void* smem_ptr) {
    uint32_t addr;
    asm("{ .reg .u64 tmp; cvta.to.shared.u64 tmp, %1; cvt.u32.u64 %0, tmp; }"
        : "=r"(addr) : "l"(smem_ptr));
    return addr;
}

__device__ __forceinline__ void cp_async16(uint32_t dst, const void* src) {
    asm volatile("cp.async.cg.shared.global [%0], [%1], 16;\n"
                 :: "r"(dst), "l"(src) : "memory");
}

__device__ __forceinline__ void ldsm_x4(uint32_t r[4], uint32_t addr) {
    asm volatile("ldmatrix.sync.aligned.m8n8.x4.shared.b16 {%0,%1,%2,%3}, [%4];"
                 : "=r"(r[0]), "=r"(r[1]), "=r"(r[2]), "=r"(r[3]) : "r"(addr));
}

__device__ __forceinline__ void mma_fp16(float acc[4], const uint32_t a[4], const uint32_t b[2]) {
    asm volatile(
        "mma.sync.aligned.m16n8k16.row.col.f32.f16.f16.f32 "
        "{%0,%1,%2,%3}, {%4,%5,%6,%7}, {%8,%9}, {%0,%1,%2,%3};"
        : "+f"(acc[0]), "+f"(acc[1]), "+f"(acc[2]), "+f"(acc[3])
        : "r"(a[0]), "r"(a[1]), "r"(a[2]), "r"(a[3]), "r"(b[0]), "r"(b[1]));
}

__device__ __forceinline__ uint32_t pack_h2(float v0, float v1) {
    fp16 h0 = __float2half(v0);
    fp16 h1 = __float2half(v1);
    return (uint32_t)__half_as_ushort(h0) | ((uint32_t)__half_as_ushort(h1) << 16);
}
__device__ __forceinline__ uint32_t pack_l2(float v0, float v1) {
    fp16 h0 = __float2half(v0);
    fp16 h1 = __float2half(v1);
    fp16 l0 = __float2half(v0 - __half2float(h0));
    fp16 l1 = __float2half(v1 - __half2float(h1));
    return (uint32_t)__half_as_ushort(l0) | ((uint32_t)__half_as_ushort(l1) << 16);
}
__device__ __forceinline__ uint2 pack_h4(float a, float b, float c, float d) {
    return make_uint2(pack_h2(a, b), pack_h2(c, d));
}
__device__ __forceinline__ uint2 pack_l4(float a, float b, float c, float d) {
    return make_uint2(pack_l2(a, b), pack_l2(c, d));
}

// ================= scratch (device globals; no allocation) ====================
__device__ __align__(128) float g_Q  [S_ * H_];
__device__ __align__(128) float g_K  [S_ * DH_];
__device__ __align__(128) float g_V  [S_ * DH_];

__device__ __align__(128) fp16 g_xh  [S_ * H_];            // x single fp16
__device__ __align__(128) fp16 g_wqT [H_ * H_];            // weights single fp16
__device__ __align__(128) fp16 g_wkT [DH_ * H_];
__device__ __align__(128) fp16 g_wvT [DH_ * H_];
__device__ __align__(128) fp16 g_woT [H_ * H_];
__device__ __align__(128) fp16 g_qhi [S_ * H_];            // Q/K keep hi/lo for QK
__device__ __align__(128) fp16 g_qlo [S_ * H_];
__device__ __align__(128) fp16 g_khi [S_ * DH_];
__device__ __align__(128) fp16 g_klo [S_ * DH_];
__device__ __align__(128) fp16 g_vt  [DH_ * S_];           // V^T single
__device__ __align__(128) fp16 g_ph  [(long long)NH_ * S_ * S_];   // P single
__device__ __align__(128) fp16 g_ch  [S_ * H_];                    // ctx single

// ================= fp16 mma.sync GEMM, 4-stage pipeline =======================
// SPLIT3=true : 3-pass (Ahi+Alo)@(Bhi+Blo) ~ hh+hl+lh   (QK only)
// SPLIT3=false: 1-pass A@B, both single fp16
// A: M x K (K-major, lda); B: N x K (K-major, ldb).
// Output: fp32 C (ldc) and/or fp16 Ch (ldc).
// mode bit0: causal tile skip; bit1: causal K limit.
template<int NT8, bool SPLIT3>
__global__ __launch_bounds__(256, 2)
void mma_gemm(const fp16* __restrict__ Ahi, const fp16* __restrict__ Alo,
              const fp16* __restrict__ Bhi, const fp16* __restrict__ Blo,
              float* __restrict__ C, fp16* __restrict__ Ch,
              int K, int lda, int ldb, int ldc,
              long long aStride, long long bStride, long long cStride,
              int mode)
{
    constexpr int TN     = NT8 * 32;
    constexpr int ROW    = 24;                 // fp16 per smem row (48B, conflict-free)
    constexpr int A_TILE = 128 * ROW;
    constexpr int B_TILE = TN * ROW;
    constexpr int NOPS   = SPLIT3 ? 2 : 1;     // operand copies (hi[,lo])
    constexpr int STAGE  = NOPS * (A_TILE + B_TILE);

    const int rowBase = blockIdx.y * 128;
    const int colBase = blockIdx.x * TN;

    if ((mode & 1) && colBase > rowBase + 127) return;

    int Keff = K;
    if (mode & 2) Keff = min(K, rowBase + 128);

    extern __shared__ fp16 smem[];
    const uint32_t sbase = smem_to_u32(smem);

    const int tid  = threadIdx.x;
    const int wid  = tid >> 5;
    const int lane = tid & 31;
    const int wm   = wid & 1;
    const int wn   = wid >> 1;

    Ahi += (long long)blockIdx.z * aStride;
    if (SPLIT3) Alo += (long long)blockIdx.z * aStride;
    Bhi += (long long)blockIdx.z * bStride;
    if (SPLIT3) Blo += (long long)blockIdx.z * bStride;

    float acc[4][NT8][4] = {};

    const int nStages = Keff >> 4;             // K-chunk = 16

    const int lrow = tid >> 1;
    const int lch  = tid & 1;

    auto issue = [&](int s) {
        const uint32_t sb = sbase + (uint32_t)(s & 3) * STAGE * 2;
        const int kt = s << 4;
        {
            const long long g = (long long)(rowBase + lrow) * lda + kt + lch * 8;
            const uint32_t d = sb + (uint32_t)(lrow * ROW + lch * 8) * 2;
            cp_async16(d, Ahi + g);
            if (SPLIT3) cp_async16(d + A_TILE * 2, Alo + g);
        }
        if (TN == 128 || tid < 128) {
            const long long g = (long long)(colBase + lrow) * ldb + kt + lch * 8;
            const uint32_t d = sb + (uint32_t)(NOPS * A_TILE + lrow * ROW + lch * 8) * 2;
            cp_async16(d, Bhi + g);
            if (SPLIT3) cp_async16(d + B_TILE * 2, Blo + g);
        }
        asm volatile("cp.async.commit_group;\n" ::: "memory");
    };

    issue(0);
    if (1 < nStages) issue(1);
    if (2 < nStages) issue(2);

    for (int s = 0; s < nStages; s++) {
        const int remain = nStages - 1 - s;
        if (remain >= 2)      asm volatile("cp.async.wait_group 2;\n" ::: "memory");
        else if (remain == 1) asm volatile("cp.async.wait_group 1;\n" ::: "memory");
        else                  asm volatile("cp.async.wait_group 0;\n" ::: "memory");
        __syncthreads();

        const uint32_t sb = sbase + (uint32_t)(s & 3) * STAGE * 2;
        const uint32_t sA = sb;
        const uint32_t sB = sb + NOPS * A_TILE * 2;

        const int arow = wm * 64 + (lane & 15);
        const int acol = ((lane >> 4) << 3);
        const int brow4 = wn * (NT8 * 8) + ((lane >> 4) << 3) + (lane & 7);
        const int bcol4 = (((lane >> 3) & 1) << 3);

        if (!SPLIT3) {
            // ---- 1-pass: all frags up front, 16 independent MMAs ----
            uint32_t bh[NT8][2];
            #pragma unroll
            for (int ntp = 0; ntp < NT8 / 2; ntp++) {
                const uint32_t addr =
                    sB + (uint32_t)((brow4 + ntp * 16) * ROW + bcol4) * 2;
                uint32_t rh[4];
                ldsm_x4(rh, addr);
                bh[2 * ntp][0] = rh[0]; bh[2 * ntp][1] = rh[1];
                bh[2 * ntp + 1][0] = rh[2]; bh[2 * ntp + 1][1] = rh[3];
            }
            uint32_t ah[4][4];
            #pragma unroll
            for (int mt = 0; mt < 4; mt++) {
                const uint32_t addr = sA + (uint32_t)((arow + mt * 16) * ROW + acol) * 2;
                ldsm_x4(ah[mt], addr);
            }
            #pragma unroll
            for (int mt = 0; mt < 4; mt++)
                #pragma unroll
                for (int nt = 0; nt < NT8; nt++)
                    mma_fp16(acc[mt][nt], ah[mt], bh[nt]);
        } else {
            // ---- 3-pass: hh + hl + lh, pass-major within mt ----
            uint32_t bh[NT8][2], bl[NT8][2];
            #pragma unroll
            for (int ntp = 0; ntp < NT8 / 2; ntp++) {
                const uint32_t addr =
                    sB + (uint32_t)((brow4 + ntp * 16) * ROW + bcol4) * 2;
                uint32_t rh[4], rl[4];
                ldsm_x4(rh, addr);
                ldsm_x4(rl, addr + B_TILE * 2);
                bh[2 * ntp][0] = rh[0]; bh[2 * ntp][1] = rh[1];
                bh[2 * ntp + 1][0] = rh[2]; bh[2 * ntp + 1][1] = rh[3];
                bl[2 * ntp][0] = rl[0]; bl[2 * ntp][1] = rl[1];
                bl[2 * ntp + 1][0] = rl[2]; bl[2 * ntp + 1][1] = rl[3];
            }
            #pragma unroll
            for (int mt = 0; mt < 4; mt++) {
                const uint32_t addr = sA + (uint32_t)((arow + mt * 16) * ROW + acol) * 2;
                uint32_t ah[4], al[4];
                ldsm_x4(ah, addr);
                ldsm_x4(al, addr + A_TILE * 2);
                #pragma unroll
                for (int nt = 0; nt < NT8; nt++)
                    mma_fp16(acc[mt][nt], ah, bh[nt]);
                #pragma unroll
                for (int nt = 0; nt < NT8; nt++)
                    mma_fp16(acc[mt][nt], ah, bl[nt]);
                #pragma unroll
                for (int nt = 0; nt < NT8; nt++)
                    mma_fp16(acc[mt][nt], al, bh[nt]);
            }
        }

        if (s + 3 < nStages) issue(s + 3);
    }

    const int erow0 = rowBase + wm * 64 + (lane >> 2);
    const int ecol0 = colBase + wn * (NT8 * 8) + (lane & 3) * 2;
    #pragma unroll
    for (int mt = 0; mt < 4; mt++) {
        #pragma unroll
        for (int nt = 0; nt < NT8; nt++) {
            const int r = erow0 + mt * 16;
            const int c = ecol0 + nt * 8;
            if (C) {
                float* Cb = C + (long long)blockIdx.z * cStride;
                *(float2*)&Cb[(long long)r * ldc + c] =
                    make_float2(acc[mt][nt][0], acc[mt][nt][1]);
                *(float2*)&Cb[(long long)(r + 8) * ldc + c] =
                    make_float2(acc[mt][nt][2], acc[mt][nt][3]);
            }
            if (Ch) {
                fp16* Hb = Ch + (long long)blockIdx.z * cStride;
                *(uint32_t*)&Hb[(long long)r * ldc + c] = pack_h2(acc[mt][nt][0], acc[mt][nt][1]);
                *(uint32_t*)&Hb[(long long)(r + 8) * ldc + c] = pack_h2(acc[mt][nt][2], acc[mt][nt][3]);
            }
        }
    }
}

// ================= fp32 -> fp16 single convert (float4 vectorized) ============
__global__ void convert_kernel(const float4* __restrict__ in,
                               uint2* __restrict__ h, long long n4)
{
    long long i = (long long)blockIdx.x * blockDim.x + threadIdx.x;
    if (i >= n4) return;
    float4 v = in[i];
    h[i] = pack_h4(v.x, v.y, v.z, v.w);
}

// transpose + convert: in[R][C] fp32 -> hT [C][R] single fp16
__global__ void tconvert_kernel(const float* __restrict__ in,
                                fp16* __restrict__ hT, int R, int C)
{
    __shared__ float tile[32][36];
    const int c0 = blockIdx.x * 32;
    const int r0 = blockIdx.y * 32;
    const int tx = threadIdx.x;
    const int ty = threadIdx.y;

    {
        float4 v = *(const float4*)&in[(long long)(r0 + tx) * C + c0 + ty * 4];
        *(float4*)&tile[tx][ty * 4] = v;
    }
    __syncthreads();
    {
        float a = tile[ty * 4 + 0][tx];
        float b = tile[ty * 4 + 1][tx];
        float c = tile[ty * 4 + 2][tx];
        float d = tile[ty * 4 + 3][tx];
        const long long o = (long long)(c0 + tx) * R + r0 + ty * 4;
        *(uint2*)&hT[o] = pack_h4(a, b, c, d);
    }
}

// ================= RoPE (fp32 in -> fp16 hi/lo out, for 3-pass QK) ============
__global__ void rope_split_kernel(const float* __restrict__ src,
                                  fp16* __restrict__ hi, fp16* __restrict__ lo,
                                  const int* __restrict__ pos,
                                  int nHeads, int rowStride)
{
    long long idx = (long long)blockIdx.x * blockDim.x + threadIdx.x;
    const long long total = (long long)S_ * nHeads * 32;
    if (idx >= total) return;
    const int d4 = (int)(idx & 31) * 4;
    const int h  = (int)((idx >> 5) % nHeads);
    const int s  = (int)(idx / (32LL * nHeads));

    const float p = (float)pos[s];
    const long long base = (long long)s * rowStride + h * DH_;

    float4 a = *(const float4*)&src[base + d4];
    float4 b = *(const float4*)&src[base + d4 + 128];

    float ra[4], rb[4];
    const float av[4] = {a.x, a.y, a.z, a.w};
    const float bv[4] = {b.x, b.y, b.z, b.w};
    #pragma unroll
    for (int k = 0; k < 4; k++) {
        const int d = d4 + k;
        float inv = exp2f(-((float)(2 * d) / (float)DH_) * log2f(10000.0f));
        float ang = p * inv;
        float sn, cs;
        sincosf(ang, &sn, &cs);
        ra[k] = av[k] * cs - bv[k] * sn;
        rb[k] = bv[k] * cs + av[k] * sn;
    }

    *(uint2*)&hi[base + d4]       = pack_h4(ra[0], ra[1], ra[2], ra[3]);
    *(uint2*)&lo[base + d4]       = pack_l4(ra[0], ra[1], ra[2], ra[3]);
    *(uint2*)&hi[base + d4 + 128] = pack_h4(rb[0], rb[1], rb[2], rb[3]);
    *(uint2*)&lo[base + d4 + 128] = pack_l4(rb[0], rb[1], rb[2], rb[3]);
}

// ================= causal scale + softmax (fp32 out + single fp16 P) ==========
__global__ void softmax_kernel(float* __restrict__ attn, fp16* __restrict__ ph)
{
    const int i = blockIdx.x;
    const int h = blockIdx.y;
    const long long rowOff = ((long long)h * S_ + i) * S_;
    float* row = attn + rowOff;
    const int t = threadIdx.x;
    const int lane = t & 31, warp = t >> 5;

    const int kLimit = ((i >> 7) + 1) << 7;

    float vals[8];
    float mx = -INFINITY;
    #pragma unroll
    for (int j = 0; j < 2; j++) {
        const int col4 = 4 * t + j * 1024;
        if (col4 <= i) {
            float4 v = *(const float4*)&row[col4];
            const float vv[4] = {v.x, v.y, v.z, v.w};
            #pragma unroll
            for (int k = 0; k < 4; k++) {
                const int col = col4 + k;
                float u = (col <= i) ? fmaf(vv[k], SCALE_, 0.0f) : NEG_;
                vals[j * 4 + k] = u;
                mx = fmaxf(mx, u);
            }
        } else {
            #pragma unroll
            for (int k = 0; k < 4; k++) vals[j * 4 + k] = NEG_;
        }
    }

    __shared__ float red[8];
    #pragma unroll
    for (int o = 16; o > 0; o >>= 1)
        mx = fmaxf(mx, __shfl_xor_sync(0xffffffffu, mx, o));
    if (lane == 0) red[warp] = mx;
    __syncthreads();
    {
        float m = red[lane & 7];
        #pragma unroll
        for (int o = 4; o > 0; o >>= 1)
            m = fmaxf(m, __shfl_xor_sync(0xffffffffu, m, o));
        mx = m;
    }

    float sum = 0.0f;
    #pragma unroll
    for (int j = 0; j < 8; j++) {
        vals[j] = __expf(vals[j] - mx);
        sum += vals[j];
    }
    #pragma unroll
    for (int o = 16; o > 0; o >>= 1)
        sum += __shfl_xor_sync(0xffffffffu, sum, o);
    __syncthreads();
    if (lane == 0) red[warp] = sum;
    __syncthreads();
    {
        float m = red[lane & 7];
        #pragma unroll
        for (int o = 4; o > 0; o >>= 1)
            m += __shfl_xor_sync(0xffffffffu, m, o);
        sum = m;
    }

    const float inv = 1.0f / sum;
    #pragma unroll
    for (int j = 0; j < 2; j++) {
        const int col4 = 4 * t + j * 1024;
        float p0 = vals[j * 4 + 0] * inv;
        float p1 = vals[j * 4 + 1] * inv;
        float p2 = vals[j * 4 + 2] * inv;
        float p3 = vals[j * 4 + 3] * inv;
        *(float4*)&row[col4] = make_float4(p0, p1, p2, p3);
        if (col4 < kLimit)
            *(uint2*)&ph[rowOff + col4] = pack_h4(p0, p1, p2, p3);
    }
}

// ================= launch ======================================================
static void* sym_addr(const void* sym)
{
    void* p = nullptr;
    cudaGetSymbolAddress(&p, sym);
    return p;
}

extern "C" void kernel_launch(void* const* d_in, const int* in_sizes, int n_in,
                              void* d_out, int out_size)
{
    const float* x    = (const float*)d_in[0];
    const int*   pos  = (const int*)  d_in[1];
    const float* wq   = (const float*)d_in[3];
    const float* wk   = (const float*)d_in[4];
    const float* wv   = (const float*)d_in[5];
    const float* wo   = (const float*)d_in[6];

    float* out  = (float*)d_out;
    float* attn = out + (long long)B_ * S_ * H_;

    float* Qf = (float*)sym_addr(g_Q);
    float* Kf = (float*)sym_addr(g_K);
    float* Vf = (float*)sym_addr(g_V);

    fp16* xh   = (fp16*)sym_addr(g_xh);
    fp16* wqT  = (fp16*)sym_addr(g_wqT);
    fp16* wkT  = (fp16*)sym_addr(g_wkT);
    fp16* wvT  = (fp16*)sym_addr(g_wvT);
    fp16* woT  = (fp16*)sym_addr(g_woT);
    fp16* qhi  = (fp16*)sym_addr(g_qhi);
    fp16* qlo  = (fp16*)sym_addr(g_qlo);
    fp16* khi  = (fp16*)sym_addr(g_khi);
    fp16* klo  = (fp16*)sym_addr(g_klo);
    fp16* vt   = (fp16*)sym_addr(g_vt);
    fp16* ph   = (fp16*)sym_addr(g_ph);
    fp16* ch   = (fp16*)sym_addr(g_ch);

    // smem: 4 stages
    const int smem1p128 = 4 * (128 * 24 + 128 * 24) * 2;      // 49152 (1-pass, TN=128)
    const int smem1p64  = 4 * (128 * 24 +  64 * 24) * 2;      // 36864 (1-pass, TN=64)
    const int smem3p128 = 4 * 2 * (128 * 24 + 128 * 24) * 2;  // 98304 (3-pass, TN=128)
    cudaFuncSetAttribute(mma_gemm<4,false>, cudaFuncAttributeMaxDynamicSharedMemorySize, smem1p128);
    cudaFuncSetAttribute(mma_gemm<2,false>, cudaFuncAttributeMaxDynamicSharedMemorySize, smem1p64);
    cudaFuncSetAttribute(mma_gemm<4,true>,  cudaFuncAttributeMaxDynamicSharedMemorySize, smem3p128);

    const long long SS  = (long long)S_ * S_;
    const long long nSH = (long long)S_ * H_;

    // ---- prep: Q-proj GEMM stays at launch #3 for ncu capture ----
    convert_kernel<<<(unsigned)((nSH / 4 + 255) / 256), 256>>>(           // #0
        (const float4*)x, (uint2*)xh, nSH / 4);
    tconvert_kernel<<<dim3(H_ / 32,  H_ / 32), dim3(32, 8)>>>(wq, wqT, H_, H_);   // #1
    tconvert_kernel<<<dim3(DH_ / 32, H_ / 32), dim3(32, 8)>>>(wk, wkT, H_, DH_);  // #2

    // ---- Q-proj (1-pass): launch #3 ----
    mma_gemm<4,false><<<dim3(H_ / 128, S_ / 128, 1), 256, smem1p128>>>(
        xh, nullptr, wqT, nullptr, Qf, nullptr, H_, H_, H_, H_, 0, 0, 0, 0);

    tconvert_kernel<<<dim3(DH_ / 32, H_ / 32), dim3(32, 8)>>>(wv, wvT, H_, DH_);
    {
        const long long bS = (long long)(wvT - wkT);
        const long long cS = (long long)(Vf - Kf);
        mma_gemm<2,false><<<dim3(DH_ / 64, S_ / 128, 2), 256, smem1p64>>>(
            xh, nullptr, wkT, nullptr, Kf, nullptr, H_, H_, H_, DH_, 0, bS, cS, 0);
    }

    // ---- RoPE -> fp16 hi/lo (for 3-pass QK) ----
    rope_split_kernel<<<(unsigned)(((long long)S_ * NH_ * 32 + 255) / 256), 256>>>(
        Qf, qhi, qlo, pos, NH_, H_);
    rope_split_kernel<<<(unsigned)(((long long)S_ * 32 + 255) / 256), 256>>>(
        Kf, khi, klo, pos, 1, DH_);

    // ---- V transpose (single fp16) ----
    tconvert_kernel<<<dim3(DH_ / 32, S_ / 32), dim3(32, 8)>>>(Vf, vt, S_, DH_);

    // ---- scores: attn_h = Q_h @ K^T (3-pass, causal tile skip) ----
    mma_gemm<4,true><<<dim3(S_ / 128, S_ / 128, NH_), 256, smem3p128>>>(
        qhi, qlo, khi, klo, attn, nullptr, DH_, H_, DH_, S_, DH_, 0, SS, 1);

    // ---- softmax (analytic causal mask, single fp16 P) ----
    softmax_kernel<<<dim3(S_, NH_), 256>>>(attn, ph);

    // ---- ctx_h = P_h @ V (1-pass, causal K-limit, fp16 ctx epilogue) ----
    mma_gemm<4,false><<<dim3(DH_ / 128, S_ / 128, NH_), 256, smem1p128>>>(
        ph, nullptr, vt, nullptr, nullptr, ch, S_, S_, S_, H_, SS, 0, DH_, 2);

    // ---- wo transpose, then out = ctx @ w_o (1-pass) ----
    tconvert_kernel<<<dim3(H_ / 32, H_ / 32), dim3(32, 8)>>>(wo, woT, H_, H_);
    mma_gemm<4,false><<<dim3(H_ / 128, S_ / 128, 1), 256, smem1p128>>>(
        ch, nullptr, woT, nullptr, out, nullptr, H_, H_, H_, H_, 0, 0, 0, 0);
}

// round 13
// speedup vs baseline: 1.8745x; 1.0629x over previous
#include <cuda_runtime.h>
#include <cuda_fp16.h>
#include <cstdint>
#include <math.h>

// Problem constants
#define B_  1
#define S_  2048
#define H_  2048
#define NH_ 8
#define DH_ 256
#define SCALE_ 0.0625f   // 256^-0.5
#define NEG_  -1000000000.0f

typedef __half fp16;

// ================= helpers =====================================================
__device__ __forceinline__ uint32_t smem_to_u32(const void* smem_ptr) {
    uint32_t addr;
    asm("{ .reg .u64 tmp; cvta.to.shared.u64 tmp, %1; cvt.u32.u64 %0, tmp; }"
        : "=r"(addr) : "l"(smem_ptr));
    return addr;
}

__device__ __forceinline__ void cp_async16(uint32_t dst, const void* src) {
    asm volatile("cp.async.cg.shared.global [%0], [%1], 16;\n"
                 :: "r"(dst), "l"(src) : "memory");
}

__device__ __forceinline__ void ldsm_x4(uint32_t r[4], uint32_t addr) {
    asm volatile("ldmatrix.sync.aligned.m8n8.x4.shared.b16 {%0,%1,%2,%3}, [%4];"
                 : "=r"(r[0]), "=r"(r[1]), "=r"(r[2]), "=r"(r[3]) : "r"(addr));
}

__device__ __forceinline__ void mma_fp16(float acc[4], const uint32_t a[4], const uint32_t b[2]) {
    asm volatile(
        "mma.sync.aligned.m16n8k16.row.col.f32.f16.f16.f32 "
        "{%0,%1,%2,%3}, {%4,%5,%6,%7}, {%8,%9}, {%0,%1,%2,%3};"
        : "+f"(acc[0]), "+f"(acc[1]), "+f"(acc[2]), "+f"(acc[3])
        : "r"(a[0]), "r"(a[1]), "r"(a[2]), "r"(a[3]), "r"(b[0]), "r"(b[1]));
}

__device__ __forceinline__ uint32_t pack_h2(float v0, float v1) {
    fp16 h0 = __float2half(v0);
    fp16 h1 = __float2half(v1);
    return (uint32_t)__half_as_ushort(h0) | ((uint32_t)__half_as_ushort(h1) << 16);
}
__device__ __forceinline__ uint32_t pack_l2(float v0, float v1) {
    fp16 h0 = __float2half(v0);
    fp16 h1 = __float2half(v1);
    fp16 l0 = __float2half(v0 - __half2float(h0));
    fp16 l1 = __float2half(v1 - __half2float(h1));
    return (uint32_t)__half_as_ushort(l0) | ((uint32_t)__half_as_ushort(l1) << 16);
}
__device__ __forceinline__ uint2 pack_h4(float a, float b, float c, float d) {
    return make_uint2(pack_h2(a, b), pack_h2(c, d));
}
__device__ __forceinline__ uint2 pack_l4(float a, float b, float c, float d) {
    return make_uint2(pack_l2(a, b), pack_l2(c, d));
}

// ================= scratch (device globals; no allocation) ====================
__device__ __align__(128) float g_Q  [S_ * H_];
__device__ __align__(128) float g_K  [S_ * DH_];
__device__ __align__(128) float g_V  [S_ * DH_];

__device__ __align__(128) fp16 g_xh  [S_ * H_];            // x single fp16
__device__ __align__(128) fp16 g_wqT [H_ * H_];            // weights single fp16
__device__ __align__(128) fp16 g_wkT [DH_ * H_];
__device__ __align__(128) fp16 g_wvT [DH_ * H_];
__device__ __align__(128) fp16 g_woT [H_ * H_];
__device__ __align__(128) fp16 g_qh  [S_ * H_];            // Q single fp16
__device__ __align__(128) fp16 g_khi [S_ * DH_];           // K hi/lo for 2-pass QK
__device__ __align__(128) fp16 g_klo [S_ * DH_];
__device__ __align__(128) fp16 g_vt  [DH_ * S_];           // V^T single
__device__ __align__(128) fp16 g_ph  [(long long)NH_ * S_ * S_];   // P single
__device__ __align__(128) fp16 g_ch  [S_ * H_];                    // ctx single

// ================= fp16 mma.sync GEMM, 4-stage pipeline =======================
// NPASS=1: A@B (both single)
// NPASS=2: A@(Bhi+Blo)  (A single, B hi/lo)       — QK
// A: M x K (K-major, lda); B: N x K (K-major, ldb).
// Output: fp32 C (ldc) and/or fp16 Ch (ldc).
// mode bit0: causal tile skip; bit1: causal K limit.
template<int NT8, int NPASS>
__global__ __launch_bounds__(256, 2)
void mma_gemm(const fp16* __restrict__ A_, const fp16* __restrict__ Bhi,
              const fp16* __restrict__ Blo,
              float* __restrict__ C, fp16* __restrict__ Ch,
              int K, int lda, int ldb, int ldc,
              long long aStride, long long bStride, long long cStride,
              int mode)
{
    constexpr int TN     = NT8 * 32;
    constexpr int ROW    = 24;                 // fp16 per smem row (48B, conflict-free)
    constexpr int A_TILE = 128 * ROW;
    constexpr int B_TILE = TN * ROW;
    constexpr int NB     = (NPASS >= 2) ? 2 : 1;
    constexpr int STAGE  = A_TILE + NB * B_TILE;

    const int rowBase = blockIdx.y * 128;
    const int colBase = blockIdx.x * TN;

    if ((mode & 1) && colBase > rowBase + 127) return;

    int Keff = K;
    if (mode & 2) Keff = min(K, rowBase + 128);

    extern __shared__ fp16 smem[];
    const uint32_t sbase = smem_to_u32(smem);

    const int tid  = threadIdx.x;
    const int wid  = tid >> 5;
    const int lane = tid & 31;
    const int wm   = wid & 1;
    const int wn   = wid >> 1;

    A_  += (long long)blockIdx.z * aStride;
    Bhi += (long long)blockIdx.z * bStride;
    if (NPASS >= 2) Blo += (long long)blockIdx.z * bStride;

    float acc[4][NT8][4] = {};

    const int nStages = Keff >> 4;             // K-chunk = 16

    const int lrow = tid >> 1;
    const int lch  = tid & 1;

    auto issue = [&](int s) {
        const uint32_t sb = sbase + (uint32_t)(s & 3) * STAGE * 2;
        const int kt = s << 4;
        {
            const long long g = (long long)(rowBase + lrow) * lda + kt + lch * 8;
            const uint32_t d = sb + (uint32_t)(lrow * ROW + lch * 8) * 2;
            cp_async16(d, A_ + g);
        }
        if (TN == 128 || tid < 128) {
            const long long g = (long long)(colBase + lrow) * ldb + kt + lch * 8;
            const uint32_t d = sb + (uint32_t)(A_TILE + lrow * ROW + lch * 8) * 2;
            cp_async16(d, Bhi + g);
            if (NPASS >= 2) cp_async16(d + B_TILE * 2, Blo + g);
        }
        asm volatile("cp.async.commit_group;\n" ::: "memory");
    };

    issue(0);
    if (1 < nStages) issue(1);
    if (2 < nStages) issue(2);

    for (int s = 0; s < nStages; s++) {
        const int remain = nStages - 1 - s;
        if (remain >= 2)      asm volatile("cp.async.wait_group 2;\n" ::: "memory");
        else if (remain == 1) asm volatile("cp.async.wait_group 1;\n" ::: "memory");
        else                  asm volatile("cp.async.wait_group 0;\n" ::: "memory");
        __syncthreads();

        const uint32_t sb = sbase + (uint32_t)(s & 3) * STAGE * 2;
        const uint32_t sA = sb;
        const uint32_t sB = sb + A_TILE * 2;

        const int arow = wm * 64 + (lane & 15);
        const int acol = ((lane >> 4) << 3);
        const int brow4 = wn * (NT8 * 8) + ((lane >> 4) << 3) + (lane & 7);
        const int bcol4 = (((lane >> 3) & 1) << 3);

        // ---- B fragments (hi [+ lo]) ----
        uint32_t bh[NT8][2], bl[NT8][2];
        #pragma unroll
        for (int ntp = 0; ntp < NT8 / 2; ntp++) {
            const uint32_t addr =
                sB + (uint32_t)((brow4 + ntp * 16) * ROW + bcol4) * 2;
            uint32_t rh[4];
            ldsm_x4(rh, addr);
            bh[2 * ntp][0] = rh[0]; bh[2 * ntp][1] = rh[1];
            bh[2 * ntp + 1][0] = rh[2]; bh[2 * ntp + 1][1] = rh[3];
            if (NPASS >= 2) {
                uint32_t rl[4];
                ldsm_x4(rl, addr + B_TILE * 2);
                bl[2 * ntp][0] = rl[0]; bl[2 * ntp][1] = rl[1];
                bl[2 * ntp + 1][0] = rl[2]; bl[2 * ntp + 1][1] = rl[3];
            }
        }
        // ---- A fragments (single) ----
        uint32_t ah[4][4];
        #pragma unroll
        for (int mt = 0; mt < 4; mt++) {
            const uint32_t addr = sA + (uint32_t)((arow + mt * 16) * ROW + acol) * 2;
            ldsm_x4(ah[mt], addr);
        }
        // ---- MMA: pass-major (16 independent accumulators per pass) ----
        #pragma unroll
        for (int mt = 0; mt < 4; mt++)
            #pragma unroll
            for (int nt = 0; nt < NT8; nt++)
                mma_fp16(acc[mt][nt], ah[mt], bh[nt]);
        if (NPASS >= 2) {
            #pragma unroll
            for (int mt = 0; mt < 4; mt++)
                #pragma unroll
                for (int nt = 0; nt < NT8; nt++)
                    mma_fp16(acc[mt][nt], ah[mt], bl[nt]);
        }

        if (s + 3 < nStages) issue(s + 3);
    }

    const int erow0 = rowBase + wm * 64 + (lane >> 2);
    const int ecol0 = colBase + wn * (NT8 * 8) + (lane & 3) * 2;
    #pragma unroll
    for (int mt = 0; mt < 4; mt++) {
        #pragma unroll
        for (int nt = 0; nt < NT8; nt++) {
            const int r = erow0 + mt * 16;
            const int c = ecol0 + nt * 8;
            if (C) {
                float* Cb = C + (long long)blockIdx.z * cStride;
                *(float2*)&Cb[(long long)r * ldc + c] =
                    make_float2(acc[mt][nt][0], acc[mt][nt][1]);
                *(float2*)&Cb[(long long)(r + 8) * ldc + c] =
                    make_float2(acc[mt][nt][2], acc[mt][nt][3]);
            }
            if (Ch) {
                fp16* Hb = Ch + (long long)blockIdx.z * cStride;
                *(uint32_t*)&Hb[(long long)r * ldc + c] = pack_h2(acc[mt][nt][0], acc[mt][nt][1]);
                *(uint32_t*)&Hb[(long long)(r + 8) * ldc + c] = pack_h2(acc[mt][nt][2], acc[mt][nt][3]);
            }
        }
    }
}

// ================= fp32 -> fp16 single convert (float4 vectorized) ============
__global__ void convert_kernel(const float4* __restrict__ in,
                               uint2* __restrict__ h, long long n4)
{
    long long i = (long long)blockIdx.x * blockDim.x + threadIdx.x;
    if (i >= n4) return;
    float4 v = in[i];
    h[i] = pack_h4(v.x, v.y, v.z, v.w);
}

// transpose + convert: in[R][C] fp32 -> hT [C][R] single fp16
__global__ void tconvert_kernel(const float* __restrict__ in,
                                fp16* __restrict__ hT, int R, int C)
{
    __shared__ float tile[32][36];
    const int c0 = blockIdx.x * 32;
    const int r0 = blockIdx.y * 32;
    const int tx = threadIdx.x;
    const int ty = threadIdx.y;

    {
        float4 v = *(const float4*)&in[(long long)(r0 + tx) * C + c0 + ty * 4];
        *(float4*)&tile[tx][ty * 4] = v;
    }
    __syncthreads();
    {
        float a = tile[ty * 4 + 0][tx];
        float b = tile[ty * 4 + 1][tx];
        float c = tile[ty * 4 + 2][tx];
        float d = tile[ty * 4 + 3][tx];
        const long long o = (long long)(c0 + tx) * R + r0 + ty * 4;
        *(uint2*)&hT[o] = pack_h4(a, b, c, d);
    }
}

// ================= RoPE (fp32 in -> fp16 hi [+lo] out) ========================
__global__ void rope_split_kernel(const float* __restrict__ src,
                                  fp16* __restrict__ hi, fp16* __restrict__ lo,
                                  const int* __restrict__ pos,
                                  int nHeads, int rowStride)
{
    long long idx = (long long)blockIdx.x * blockDim.x + threadIdx.x;
    const long long total = (long long)S_ * nHeads * 32;
    if (idx >= total) return;
    const int d4 = (int)(idx & 31) * 4;
    const int h  = (int)((idx >> 5) % nHeads);
    const int s  = (int)(idx / (32LL * nHeads));

    const float p = (float)pos[s];
    const long long base = (long long)s * rowStride + h * DH_;

    float4 a = *(const float4*)&src[base + d4];
    float4 b = *(const float4*)&src[base + d4 + 128];

    float ra[4], rb[4];
    const float av[4] = {a.x, a.y, a.z, a.w};
    const float bv[4] = {b.x, b.y, b.z, b.w};
    #pragma unroll
    for (int k = 0; k < 4; k++) {
        const int d = d4 + k;
        float inv = exp2f(-((float)(2 * d) / (float)DH_) * log2f(10000.0f));
        float ang = p * inv;
        float sn, cs;
        sincosf(ang, &sn, &cs);
        ra[k] = av[k] * cs - bv[k] * sn;
        rb[k] = bv[k] * cs + av[k] * sn;
    }

    *(uint2*)&hi[base + d4]       = pack_h4(ra[0], ra[1], ra[2], ra[3]);
    *(uint2*)&hi[base + d4 + 128] = pack_h4(rb[0], rb[1], rb[2], rb[3]);
    if (lo) {
        *(uint2*)&lo[base + d4]       = pack_l4(ra[0], ra[1], ra[2], ra[3]);
        *(uint2*)&lo[base + d4 + 128] = pack_l4(rb[0], rb[1], rb[2], rb[3]);
    }
}

// ================= causal scale + softmax (fp32 out + single fp16 P) ==========
__global__ void softmax_kernel(float* __restrict__ attn, fp16* __restrict__ ph)
{
    const int i = blockIdx.x;
    const int h = blockIdx.y;
    const long long rowOff = ((long long)h * S_ + i) * S_;
    float* row = attn + rowOff;
    const int t = threadIdx.x;
    const int lane = t & 31, warp = t >> 5;

    const int kLimit = ((i >> 7) + 1) << 7;

    float vals[8];
    float mx = -INFINITY;
    #pragma unroll
    for (int j = 0; j < 2; j++) {
        const int col4 = 4 * t + j * 1024;
        if (col4 <= i) {
            float4 v = *(const float4*)&row[col4];
            const float vv[4] = {v.x, v.y, v.z, v.w};
            #pragma unroll
            for (int k = 0; k < 4; k++) {
                const int col = col4 + k;
                float u = (col <= i) ? fmaf(vv[k], SCALE_, 0.0f) : NEG_;
                vals[j * 4 + k] = u;
                mx = fmaxf(mx, u);
            }
        } else {
            #pragma unroll
            for (int k = 0; k < 4; k++) vals[j * 4 + k] = NEG_;
        }
    }

    __shared__ float red[8];
    #pragma unroll
    for (int o = 16; o > 0; o >>= 1)
        mx = fmaxf(mx, __shfl_xor_sync(0xffffffffu, mx, o));
    if (lane == 0) red[warp] = mx;
    __syncthreads();
    {
        float m = red[lane & 7];
        #pragma unroll
        for (int o = 4; o > 0; o >>= 1)
            m = fmaxf(m, __shfl_xor_sync(0xffffffffu, m, o));
        mx = m;
    }

    float sum = 0.0f;
    #pragma unroll
    for (int j = 0; j < 8; j++) {
        vals[j] = __expf(vals[j] - mx);
        sum += vals[j];
    }
    #pragma unroll
    for (int o = 16; o > 0; o >>= 1)
        sum += __shfl_xor_sync(0xffffffffu, sum, o);
    __syncthreads();
    if (lane == 0) red[warp] = sum;
    __syncthreads();
    {
        float m = red[lane & 7];
        #pragma unroll
        for (int o = 4; o > 0; o >>= 1)
            m += __shfl_xor_sync(0xffffffffu, m, o);
        sum = m;
    }

    const float inv = 1.0f / sum;
    #pragma unroll
    for (int j = 0; j < 2; j++) {
        const int col4 = 4 * t + j * 1024;
        float p0 = vals[j * 4 + 0] * inv;
        float p1 = vals[j * 4 + 1] * inv;
        float p2 = vals[j * 4 + 2] * inv;
        float p3 = vals[j * 4 + 3] * inv;
        *(float4*)&row[col4] = make_float4(p0, p1, p2, p3);
        if (col4 < kLimit)
            *(uint2*)&ph[rowOff + col4] = pack_h4(p0, p1, p2, p3);
    }
}

// ================= launch ======================================================
static void* sym_addr(const void* sym)
{
    void* p = nullptr;
    cudaGetSymbolAddress(&p, sym);
    return p;
}

extern "C" void kernel_launch(void* const* d_in, const int* in_sizes, int n_in,
                              void* d_out, int out_size)
{
    const float* x    = (const float*)d_in[0];
    const int*   pos  = (const int*)  d_in[1];
    const float* wq   = (const float*)d_in[3];
    const float* wk   = (const float*)d_in[4];
    const float* wv   = (const float*)d_in[5];
    const float* wo   = (const float*)d_in[6];

    float* out  = (float*)d_out;
    float* attn = out + (long long)B_ * S_ * H_;

    float* Qf = (float*)sym_addr(g_Q);
    float* Kf = (float*)sym_addr(g_K);
    float* Vf = (float*)sym_addr(g_V);

    fp16* xh   = (fp16*)sym_addr(g_xh);
    fp16* wqT  = (fp16*)sym_addr(g_wqT);
    fp16* wkT  = (fp16*)sym_addr(g_wkT);
    fp16* wvT  = (fp16*)sym_addr(g_wvT);
    fp16* woT  = (fp16*)sym_addr(g_woT);
    fp16* qh   = (fp16*)sym_addr(g_qh);
    fp16* khi  = (fp16*)sym_addr(g_khi);
    fp16* klo  = (fp16*)sym_addr(g_klo);
    fp16* vt   = (fp16*)sym_addr(g_vt);
    fp16* ph   = (fp16*)sym_addr(g_ph);
    fp16* ch   = (fp16*)sym_addr(g_ch);

    // smem: 4 stages
    const int smem1p128 = 4 * (128 * 24 + 128 * 24) * 2;          // 49152
    const int smem1p64  = 4 * (128 * 24 +  64 * 24) * 2;          // 36864
    const int smem2p128 = 4 * (128 * 24 + 2 * 128 * 24) * 2;      // 73728
    cudaFuncSetAttribute(mma_gemm<4,1>, cudaFuncAttributeMaxDynamicSharedMemorySize, smem1p128);
    cudaFuncSetAttribute(mma_gemm<2,1>, cudaFuncAttributeMaxDynamicSharedMemorySize, smem1p64);
    cudaFuncSetAttribute(mma_gemm<4,2>, cudaFuncAttributeMaxDynamicSharedMemorySize, smem2p128);

    const long long SS  = (long long)S_ * S_;
    const long long nSH = (long long)S_ * H_;

    // ---- prep: Q-proj GEMM stays at launch #3 for ncu capture ----
    convert_kernel<<<(unsigned)((nSH / 4 + 255) / 256), 256>>>(           // #0
        (const float4*)x, (uint2*)xh, nSH / 4);
    tconvert_kernel<<<dim3(H_ / 32,  H_ / 32), dim3(32, 8)>>>(wq, wqT, H_, H_);   // #1
    tconvert_kernel<<<dim3(DH_ / 32, H_ / 32), dim3(32, 8)>>>(wk, wkT, H_, DH_);  // #2

    // ---- Q-proj (1-pass): launch #3 ----
    mma_gemm<4,1><<<dim3(H_ / 128, S_ / 128, 1), 256, smem1p128>>>(
        xh, wqT, nullptr, Qf, nullptr, H_, H_, H_, H_, 0, 0, 0, 0);

    tconvert_kernel<<<dim3(DH_ / 32, H_ / 32), dim3(32, 8)>>>(wv, wvT, H_, DH_);
    {
        const long long bS = (long long)(wvT - wkT);
        const long long cS = (long long)(Vf - Kf);
        mma_gemm<2,1><<<dim3(DH_ / 64, S_ / 128, 2), 256, smem1p64>>>(
            xh, wkT, nullptr, Kf, nullptr, H_, H_, H_, DH_, 0, bS, cS, 0);
    }

    // ---- RoPE: Q -> single fp16; K -> hi/lo (for 2-pass QK) ----
    rope_split_kernel<<<(unsigned)(((long long)S_ * NH_ * 32 + 255) / 256), 256>>>(
        Qf, qh, nullptr, pos, NH_, H_);
    rope_split_kernel<<<(unsigned)(((long long)S_ * 32 + 255) / 256), 256>>>(
        Kf, khi, klo, pos, 1, DH_);

    // ---- V transpose (single fp16) ----
    tconvert_kernel<<<dim3(DH_ / 32, S_ / 32), dim3(32, 8)>>>(Vf, vt, S_, DH_);

    // ---- scores: attn_h = Q_h @ K^T (2-pass: Q@Khi + Q@Klo, causal skip) ----
    mma_gemm<4,2><<<dim3(S_ / 128, S_ / 128, NH_), 256, smem2p128>>>(
        qh, khi, klo, attn, nullptr, DH_, H_, DH_, S_, DH_, 0, SS, 1);

    // ---- softmax (analytic causal mask, single fp16 P) ----
    softmax_kernel<<<dim3(S_, NH_), 256>>>(attn, ph);

    // ---- ctx_h = P_h @ V (1-pass, causal K-limit, fp16 ctx epilogue) ----
    mma_gemm<4,1><<<dim3(DH_ / 128, S_ / 128, NH_), 256, smem1p128>>>(
        ph, vt, nullptr, nullptr, ch, S_, S_, S_, H_, SS, 0, DH_, 2);

    // ---- wo transpose, then out = ctx @ w_o (1-pass) ----
    tconvert_kernel<<<dim3(H_ / 32, H_ / 32), dim3(32, 8)>>>(wo, woT, H_, H_);
    mma_gemm<4,1><<<dim3(H_ / 128, S_ / 128, 1), 256, smem1p128>>>(
        ch, woT, nullptr, out, nullptr, H_, H_, H_, H_, 0, 0, 0, 0);
}